// round 11
// baseline (speedup 1.0000x reference)
#include <cuda_runtime.h>
#include <cuda_fp16.h>
#include <cstdint>

#define N_XROWS   50000
#define N_MOTIF   10000
#define N_TOT     60000
#define E_TOT     1920000
#define NHID      256
#define PAD_N     65536
#define M_PAD     60032          // 938 * 64
#define SPLIT     30016          // 469 * 64
#define H1ROWS    (N_TOT - SPLIT)
#define ECAP      80             // per-row edge bucket capacity (Poisson(32))

// ---------------- device scratch (no allocs allowed) ----------------
__device__ int   g_cnt[N_TOT];
__device__ int2  g_edges[(size_t)N_TOT * ECAP];
__device__ __half g_support[(size_t)N_TOT * NHID];     // fp16 support
__device__ __half g_a[(size_t)M_PAD * 512];            // A operand, fp16
__device__ __half g_b1[256 * 512];                     // W1^T fp16, K-major
__device__ __half g_b2[256 * 256];                     // W2^T fp16
__device__ __half g_b3[256 * 256];                     // W3^T fp16

// ================= helpers =================
__device__ __forceinline__ uint32_t smem_u32(const void* p) {
    uint32_t a;
    asm("{ .reg .u64 t; cvta.to.shared.u64 t, %1; cvt.u32.u64 %0, t; }"
        : "=r"(a) : "l"(p));
    return a;
}
__device__ __forceinline__ void cp_async16(uint32_t dst, const void* src) {
    asm volatile("cp.async.cg.shared.global [%0], [%1], 16;"
                 :: "r"(dst), "l"(__cvta_generic_to_global(src)) : "memory");
}
#define CP_COMMIT() asm volatile("cp.async.commit_group;" ::: "memory")
#define CP_WAIT(n)  asm volatile("cp.async.wait_group %0;" :: "n"(n) : "memory")

__device__ __forceinline__ void mma16816(float* d, const uint32_t* a,
                                         const uint32_t* b) {
    asm volatile(
        "mma.sync.aligned.m16n8k16.row.col.f32.f16.f16.f32 "
        "{%0,%1,%2,%3}, {%4,%5,%6,%7}, {%8,%9}, {%0,%1,%2,%3};"
        : "+f"(d[0]), "+f"(d[1]), "+f"(d[2]), "+f"(d[3])
        : "r"(a[0]), "r"(a[1]), "r"(a[2]), "r"(a[3]), "r"(b[0]), "r"(b[1]));
}

__device__ __forceinline__ uint64_t pack4h(__half a, __half b, __half c, __half d) {
    __half2 p0 = __halves2half2(a, b);
    __half2 p1 = __halves2half2(c, d);
    uint32_t u0 = *(uint32_t*)&p0;
    uint32_t u1 = *(uint32_t*)&p1;
    return (uint64_t)u0 | ((uint64_t)u1 << 32);
}

// ---------------- bucket CSR build ----------------
__global__ void zero_cnt_kernel() {
    int i = blockIdx.x * 256 + threadIdx.x;
    if (i < N_TOT) g_cnt[i] = 0;
}
__global__ void scatter_edges_kernel(const int* __restrict__ rows,
                                     const int* __restrict__ cols,
                                     const float* __restrict__ vals) {
    int i = blockIdx.x * 256 + threadIdx.x;
    if (i < E_TOT) {
        int r = rows[i];
        int slot = atomicAdd(&g_cnt[r], 1);
        if (slot < ECAP)
            g_edges[(size_t)r * ECAP + slot] =
                make_int2(cols[i], __float_as_int(vals[i]));
    }
}

// ---------------- fp16 conversions ----------------
// converts rows [base, base+count) of the concatenated (x|motif) matrix
__global__ void convertA_kernel(const float* __restrict__ x,
                                const float* __restrict__ motif,
                                __half* __restrict__ out,
                                int base, int count) {
    int idx = blockIdx.x * 256 + threadIdx.x;      // count*128 threads
    if (idx >= count * 128) return;
    int m  = base + (idx >> 7);
    int kq = (idx & 127) << 2;
    const float* src = (m < N_XROWS)
        ? x + (size_t)m * 512 + kq
        : motif + (size_t)(m - N_XROWS) * 512 + kq;
    float4 v = *(const float4*)src;
    *(uint64_t*)(out + (size_t)m * 512 + kq) =
        pack4h(__float2half_rn(v.x), __float2half_rn(v.y),
               __float2half_rn(v.z), __float2half_rn(v.w));
}

// B [K,N=256] fp32 -> out [n][k] fp16 (B^T, K-major, stride K)
__global__ void convertB_kernel(const float* __restrict__ B, int K,
                                __half* __restrict__ out) {
    int idx = blockIdx.x * 256 + threadIdx.x;    // K*256 threads
    if (idx >= K * 256) return;
    int k = idx >> 8;
    int n = idx & 255;
    out[(size_t)n * K + k] = __float2half_rn(B[idx]);
}

// ---------------- HMMA GEMM: C[M,256] = A16 @ B16^T (1 pass) ----
// CTA tile 64x256 (full N), BK=32, 8 warps as 2(M) x 4(N), warp tile 32x64.
// 3-stage cp.async pipeline, 2 CTAs/SM, fp16 epilogue.
#define SA 40                               // padded SMEM row stride (halfs)
#define STAGE_ELEMS ((64 + 256) * SA)       // A tile + B tile (12800 halfs)
#define GEMM_SMEM   (3 * STAGE_ELEMS * 2)   // 76800 bytes

__global__ void __launch_bounds__(256, 2)
hmma_gemm_kernel(const __half* __restrict__ A,
                 const __half* __restrict__ B1,
                 __half* __restrict__ C, int K, int M) {
    extern __shared__ __half sm[];
    const int t    = threadIdx.x;
    const int lane = t & 31, wid = t >> 5;
    const int wm   = wid & 1, wn = wid >> 1;   // 2 x 4 warp grid
    const int gid  = lane >> 2, tid4 = lane & 3;
    const int row0 = blockIdx.x * 64;
    const int CC = K >> 5;            // 32-wide chunks, single pass

    float acc[2][8][4];
    #pragma unroll
    for (int mi = 0; mi < 2; mi++)
        #pragma unroll
        for (int ni = 0; ni < 8; ni++)
            #pragma unroll
            for (int q = 0; q < 4; q++) acc[mi][ni][q] = 0.f;

    auto load_chunk = [&](int stage, int koff) {
        __half* s  = sm + stage * STAGE_ELEMS;
        __half* sB = s + 64 * SA;
        {                                      // A: 64 rows x 32 halfs
            int r = t >> 2, q = t & 3;
            cp_async16(smem_u32(s + r * SA + q * 8),
                       A + (size_t)(row0 + r) * K + koff + q * 8);
        }
        #pragma unroll
        for (int j = 0; j < 4; j++) {          // B: 256 rows x 32 halfs
            int u = j * 256 + t;
            int r = u >> 2, q = u & 3;
            cp_async16(smem_u32(sB + r * SA + q * 8),
                       B1 + (size_t)r * K + koff + q * 8);
        }
        CP_COMMIT();
    };

    load_chunk(0, 0);
    load_chunk(1, 32);

    for (int c = 0; c < CC; c++) {
        if (c < CC - 1) CP_WAIT(1); else CP_WAIT(0);
        __syncthreads();
        if (c + 2 < CC) load_chunk((c + 2) % 3, (c + 2) << 5);
        const __half* s  = sm + (c % 3) * STAGE_ELEMS;
        const __half* sB = s + 64 * SA;
        #pragma unroll
        for (int ks = 0; ks < 2; ks++) {
            uint32_t a[2][4], b[8][2];
            const int kc = ks * 16 + tid4 * 2;
            #pragma unroll
            for (int mi = 0; mi < 2; mi++) {
                int r0 = wm * 32 + mi * 16 + gid;
                a[mi][0] = *(const uint32_t*)(s + (size_t)r0 * SA + kc);
                a[mi][1] = *(const uint32_t*)(s + (size_t)(r0 + 8) * SA + kc);
                a[mi][2] = *(const uint32_t*)(s + (size_t)r0 * SA + kc + 8);
                a[mi][3] = *(const uint32_t*)(s + (size_t)(r0 + 8) * SA + kc + 8);
            }
            #pragma unroll
            for (int ni = 0; ni < 8; ni++) {
                int n0 = wn * 64 + ni * 8 + gid;
                b[ni][0] = *(const uint32_t*)(sB + (size_t)n0 * SA + kc);
                b[ni][1] = *(const uint32_t*)(sB + (size_t)n0 * SA + kc + 8);
            }
            #pragma unroll
            for (int mi = 0; mi < 2; mi++)
                #pragma unroll
                for (int ni = 0; ni < 8; ni++)
                    mma16816(acc[mi][ni], a[mi], b[ni]);
        }
    }

    // epilogue -> fp16
    #pragma unroll
    for (int mi = 0; mi < 2; mi++) {
        int r = row0 + wm * 32 + mi * 16 + gid;
        #pragma unroll
        for (int ni = 0; ni < 8; ni++) {
            int cidx = wn * 64 + ni * 8 + tid4 * 2;
            if (r < M)
                *(__half2*)(C + (size_t)r * 256 + cidx) =
                    __floats2half2_rn(acc[mi][ni][0], acc[mi][ni][1]);
            if (r + 8 < M)
                *(__half2*)(C + (size_t)(r + 8) * 256 + cidx) =
                    __floats2half2_rn(acc[mi][ni][2], acc[mi][ni][3]);
        }
    }
}

// ---------------- SpMM: warp-per-row, LDG.128 gathers ----------------
__device__ __forceinline__ void fma8(float* acc, float v, uint4 raw) {
    float2 f0 = __half22float2(*(__half2*)&raw.x);
    float2 f1 = __half22float2(*(__half2*)&raw.y);
    float2 f2 = __half22float2(*(__half2*)&raw.z);
    float2 f3 = __half22float2(*(__half2*)&raw.w);
    acc[0] = fmaf(v, f0.x, acc[0]);
    acc[1] = fmaf(v, f0.y, acc[1]);
    acc[2] = fmaf(v, f1.x, acc[2]);
    acc[3] = fmaf(v, f1.y, acc[3]);
    acc[4] = fmaf(v, f2.x, acc[4]);
    acc[5] = fmaf(v, f2.y, acc[5]);
    acc[6] = fmaf(v, f3.x, acc[6]);
    acc[7] = fmaf(v, f3.y, acc[7]);
}

__device__ __forceinline__ void spmm_row_w(const uint4* __restrict__ sup4,
                                           int row, int lane, float* acc) {
    int s = row * ECAP;
    int cnt = g_cnt[row];
    cnt = (cnt < ECAP) ? cnt : ECAP;
    int e = s + cnt;
    float acc1[8];
    #pragma unroll
    for (int q = 0; q < 8; q++) { acc[q] = 0.f; acc1[q] = 0.f; }
    int i = s;
    for (; i + 4 <= e; i += 4) {
        int2 e0 = __ldg(&g_edges[i]);
        int2 e1 = __ldg(&g_edges[i + 1]);
        int2 e2 = __ldg(&g_edges[i + 2]);
        int2 e3 = __ldg(&g_edges[i + 3]);
        uint4 r0 = __ldg(&sup4[(size_t)e0.x * 32 + lane]);
        uint4 r1 = __ldg(&sup4[(size_t)e1.x * 32 + lane]);
        uint4 r2 = __ldg(&sup4[(size_t)e2.x * 32 + lane]);
        uint4 r3 = __ldg(&sup4[(size_t)e3.x * 32 + lane]);
        fma8(acc,  __int_as_float(e0.y), r0);
        fma8(acc1, __int_as_float(e1.y), r1);
        fma8(acc,  __int_as_float(e2.y), r2);
        fma8(acc1, __int_as_float(e3.y), r3);
    }
    for (; i < e; i++) {
        int2 ed = __ldg(&g_edges[i]);
        uint4 r0 = __ldg(&sup4[(size_t)ed.x * 32 + lane]);
        fma8(acc, __int_as_float(ed.y), r0);
    }
    #pragma unroll
    for (int q = 0; q < 8; q++) acc[q] += acc1[q];
}

// writes next layer's fp16 A operand (stride 256)
__global__ void __launch_bounds__(256)
spmm_h16_kernel(const uint4* __restrict__ sup4,
                const float4* __restrict__ bias,
                __half* __restrict__ a_next, int nrows) {
    const int row  = blockIdx.x * 8 + (threadIdx.x >> 5);
    const int lane = threadIdx.x & 31;
    if (row >= nrows) return;
    float acc[8];
    spmm_row_w(sup4, row, lane, acc);
    float4 b0 = __ldg(&bias[lane * 2]);
    float4 b1 = __ldg(&bias[lane * 2 + 1]);
    float v0 = fmaxf(acc[0] + b0.x, 0.f), v1 = fmaxf(acc[1] + b0.y, 0.f);
    float v2 = fmaxf(acc[2] + b0.z, 0.f), v3 = fmaxf(acc[3] + b0.w, 0.f);
    float v4 = fmaxf(acc[4] + b1.x, 0.f), v5 = fmaxf(acc[5] + b1.y, 0.f);
    float v6 = fmaxf(acc[6] + b1.z, 0.f), v7 = fmaxf(acc[7] + b1.w, 0.f);
    __half2 h0 = __floats2half2_rn(v0, v1);
    __half2 h1 = __floats2half2_rn(v2, v3);
    __half2 h2 = __floats2half2_rn(v4, v5);
    __half2 h3 = __floats2half2_rn(v6, v7);
    uint4 o;
    o.x = *(uint32_t*)&h0; o.y = *(uint32_t*)&h1;
    o.z = *(uint32_t*)&h2; o.w = *(uint32_t*)&h3;
    *(uint4*)(a_next + (size_t)row * 256 + lane * 8) = o;
}

// Layer-3 SpMM fused with the output permutation: rows < N_XROWS,
// writes relu(agg + b) directly at out[pos[row]].
__global__ void __launch_bounds__(256)
spmm_out_kernel(const uint4* __restrict__ sup4,
                const float4* __restrict__ bias,
                const int* __restrict__ pos,
                float4* __restrict__ out, int nrows) {
    const int row  = blockIdx.x * 8 + (threadIdx.x >> 5);
    const int lane = threadIdx.x & 31;
    if (row >= nrows) return;
    float acc[8];
    spmm_row_w(sup4, row, lane, acc);
    float4 b0 = __ldg(&bias[lane * 2]);
    float4 b1 = __ldg(&bias[lane * 2 + 1]);
    float4 o0, o1;
    o0.x = fmaxf(acc[0] + b0.x, 0.f); o0.y = fmaxf(acc[1] + b0.y, 0.f);
    o0.z = fmaxf(acc[2] + b0.z, 0.f); o0.w = fmaxf(acc[3] + b0.w, 0.f);
    o1.x = fmaxf(acc[4] + b1.x, 0.f); o1.y = fmaxf(acc[5] + b1.y, 0.f);
    o1.z = fmaxf(acc[6] + b1.z, 0.f); o1.w = fmaxf(acc[7] + b1.w, 0.f);
    size_t base = (size_t)__ldg(&pos[row]) * 64 + lane * 2;
    out[base]     = o0;
    out[base + 1] = o1;
}

// ---------------- output zero ----------------
__global__ void zero_out_kernel(float4* __restrict__ out, int n4) {
    int i = blockIdx.x * 256 + threadIdx.x;
    if (i < n4) out[i] = make_float4(0.f, 0.f, 0.f, 0.f);
}

// ---------------- launch ----------------
extern "C" void kernel_launch(void* const* d_in, const int* in_sizes, int n_in,
                              void* d_out, int out_size) {
    const float* x     = (const float*)d_in[0];
    const float* motif = (const float*)d_in[1];
    const int*   rows  = (const int*)d_in[2];
    const int*   cols  = (const int*)d_in[3];
    const float* vals  = (const float*)d_in[4];
    const int*   pos   = (const int*)d_in[5];
    int wi = 6;
    if (n_in >= 13 && in_sizes[6] == 1) wi = 7;
    const float* w1 = (const float*)d_in[wi + 0];
    const float* b1 = (const float*)d_in[wi + 1];
    const float* w2 = (const float*)d_in[wi + 2];
    const float* b2 = (const float*)d_in[wi + 3];
    const float* w3 = (const float*)d_in[wi + 4];
    const float* b3 = (const float*)d_in[wi + 5];

    __half *support, *a, *bt1, *bt2, *bt3;
    cudaGetSymbolAddress((void**)&support, g_support);
    cudaGetSymbolAddress((void**)&a, g_a);
    cudaGetSymbolAddress((void**)&bt1, g_b1);
    cudaGetSymbolAddress((void**)&bt2, g_b2);
    cudaGetSymbolAddress((void**)&bt3, g_b3);

    cudaFuncSetAttribute(hmma_gemm_kernel,
                         cudaFuncAttributeMaxDynamicSharedMemorySize, GEMM_SMEM);

    // ONE side stream (two-wide graph passed teardown in R9; three-wide
    // leaked graph-upload pool memory). Created per call, intentionally
    // not destroyed mid-capture.
    cudaStream_t s2;
    cudaStreamCreateWithFlags(&s2, cudaStreamNonBlocking);
    cudaEvent_t evFork, evA1, evCsr;
    cudaEventCreateWithFlags(&evFork, cudaEventDisableTiming);
    cudaEventCreateWithFlags(&evA1,   cudaEventDisableTiming);
    cudaEventCreateWithFlags(&evCsr,  cudaEventDisableTiming);

    cudaEventRecord(evFork, 0);
    cudaStreamWaitEvent(s2, evFork, 0);

    const int gemm_half = SPLIT / 64;        // 469
    const int gemm_full = M_PAD / 64;        // 938
    const int spmm_grid = (N_TOT + 7) / 8;
    const int spmo_grid = (N_XROWS + 7) / 8;
    int n4 = out_size / 4;

    // --- side chain (s2): convertA half 1 first, then bucket CSR + zero ---
    convertA_kernel<<<(H1ROWS * 128 + 255) / 256, 256, 0, s2>>>(x, motif, a,
                                                                SPLIT, H1ROWS);
    cudaEventRecord(evA1, s2);
    zero_cnt_kernel<<<(N_TOT + 255) / 256, 256, 0, s2>>>();
    scatter_edges_kernel<<<E_TOT / 256, 256, 0, s2>>>(rows, cols, vals);
    zero_out_kernel<<<(n4 + 255) / 256, 256, 0, s2>>>((float4*)d_out, n4);
    cudaEventRecord(evCsr, s2);

    // --- main chain: weights + A half 0 + layer-1 GEMM (split halves) ---
    convertB_kernel<<<512, 256>>>(w1, 512, bt1);
    convertB_kernel<<<256, 256>>>(w2, 256, bt2);
    convertB_kernel<<<256, 256>>>(w3, 256, bt3);
    convertA_kernel<<<(SPLIT * 128) / 256, 256>>>(x, motif, a, 0, SPLIT);
    hmma_gemm_kernel<<<gemm_half, 256, GEMM_SMEM>>>(a, bt1, support, 512, SPLIT);
    cudaStreamWaitEvent(0, evA1, 0);
    hmma_gemm_kernel<<<gemm_half, 256, GEMM_SMEM>>>(
        a + (size_t)SPLIT * 512, bt1, support + (size_t)SPLIT * 256,
        512, H1ROWS);

    // join: SpMM needs the bucket CSR; spmm_out needs zeroed output
    cudaStreamWaitEvent(0, evCsr, 0);
    spmm_h16_kernel<<<spmm_grid, 256>>>((const uint4*)support,
                                        (const float4*)b1, a, N_TOT);

    // --- layer 2 (K=256) ---
    hmma_gemm_kernel<<<gemm_full, 256, GEMM_SMEM>>>(a, bt2, support, 256, N_TOT);
    spmm_h16_kernel<<<spmm_grid, 256>>>((const uint4*)support,
                                        (const float4*)b2, a, N_TOT);

    // --- layer 3 (K=256): SpMM fused with output scatter ---
    hmma_gemm_kernel<<<gemm_full, 256, GEMM_SMEM>>>(a, bt3, support, 256, N_TOT);
    spmm_out_kernel<<<spmo_grid, 256>>>((const uint4*)support,
                                        (const float4*)b3, pos,
                                        (float4*)d_out, N_XROWS);
}

// round 12
// speedup vs baseline: 1.1362x; 1.1362x over previous
#include <cuda_runtime.h>
#include <cuda_fp16.h>
#include <cstdint>

#define N_XROWS   50000
#define N_MOTIF   10000
#define N_TOT     60000
#define E_TOT     1920000
#define NHID      256
#define PAD_N     65536
#define M_PAD     60032          // 938 * 64
#define SPLIT     30016          // 469 * 64
#define H1ROWS    (N_TOT - SPLIT)

// ---------------- device scratch (no allocs allowed) ----------------
__device__ int   g_cnt[N_TOT];
__device__ int   g_cur[N_TOT];
__device__ int   g_rowptr[N_TOT + 1];
__device__ int2  g_edges[E_TOT];
__device__ __half g_support[(size_t)N_TOT * NHID];     // fp16 support
__device__ __half g_a[(size_t)M_PAD * 512];            // A operand, fp16
__device__ __half g_b1[256 * 512];                     // W1^T fp16, K-major
__device__ __half g_b2[256 * 256];                     // W2^T fp16
__device__ __half g_b3[256 * 256];                     // W3^T fp16

// ================= helpers =================
__device__ __forceinline__ uint32_t smem_u32(const void* p) {
    uint32_t a;
    asm("{ .reg .u64 t; cvta.to.shared.u64 t, %1; cvt.u32.u64 %0, t; }"
        : "=r"(a) : "l"(p));
    return a;
}
__device__ __forceinline__ void cp_async16(uint32_t dst, const void* src) {
    asm volatile("cp.async.cg.shared.global [%0], [%1], 16;"
                 :: "r"(dst), "l"(__cvta_generic_to_global(src)) : "memory");
}
#define CP_COMMIT() asm volatile("cp.async.commit_group;" ::: "memory")
#define CP_WAIT(n)  asm volatile("cp.async.wait_group %0;" :: "n"(n) : "memory")

__device__ __forceinline__ void mma16816(float* d, const uint32_t* a,
                                         const uint32_t* b) {
    asm volatile(
        "mma.sync.aligned.m16n8k16.row.col.f32.f16.f16.f32 "
        "{%0,%1,%2,%3}, {%4,%5,%6,%7}, {%8,%9}, {%0,%1,%2,%3};"
        : "+f"(d[0]), "+f"(d[1]), "+f"(d[2]), "+f"(d[3])
        : "r"(a[0]), "r"(a[1]), "r"(a[2]), "r"(a[3]), "r"(b[0]), "r"(b[1]));
}

__device__ __forceinline__ uint64_t pack4h(__half a, __half b, __half c, __half d) {
    __half2 p0 = __halves2half2(a, b);
    __half2 p1 = __halves2half2(c, d);
    uint32_t u0 = *(uint32_t*)&p0;
    uint32_t u1 = *(uint32_t*)&p1;
    return (uint64_t)u0 | ((uint64_t)u1 << 32);
}

// ---------------- CSR build (packed; small L2 footprint) ----------------
__global__ void zero_cnt_kernel() {
    int i = blockIdx.x * 256 + threadIdx.x;
    if (i < N_TOT) { g_cnt[i] = 0; g_cur[i] = 0; }
}
__global__ void hist_kernel(const int* __restrict__ rows) {
    int i = blockIdx.x * 256 + threadIdx.x;
    if (i < E_TOT) atomicAdd(&g_cnt[rows[i]], 1);
}
__global__ void scan_kernel() {
    __shared__ int wsum[32];
    __shared__ int chunk_total;
    __shared__ int s_running;
    const int tid = threadIdx.x;
    const int lane = tid & 31, wid = tid >> 5;
    if (tid == 0) s_running = 0;
    __syncthreads();
    for (int base = 0; base < N_TOT; base += 1024) {
        int i = base + tid;
        int x = (i < N_TOT) ? g_cnt[i] : 0;
        int v = x;
        #pragma unroll
        for (int off = 1; off < 32; off <<= 1) {
            int u = __shfl_up_sync(0xffffffffu, v, off);
            if (lane >= off) v += u;
        }
        if (lane == 31) wsum[wid] = v;
        __syncthreads();
        if (wid == 0) {
            int w = wsum[lane];
            #pragma unroll
            for (int off = 1; off < 32; off <<= 1) {
                int u = __shfl_up_sync(0xffffffffu, w, off);
                if (lane >= off) w += u;
            }
            wsum[lane] = w;
            if (lane == 31) chunk_total = w;
        }
        __syncthreads();
        int warp_prefix = (wid == 0) ? 0 : wsum[wid - 1];
        int excl = s_running + warp_prefix + v - x;
        if (i < N_TOT) g_rowptr[i] = excl;
        __syncthreads();
        if (tid == 0) s_running += chunk_total;
        __syncthreads();
    }
    if (tid == 0) g_rowptr[N_TOT] = s_running;
}
__global__ void scatter_edges_kernel(const int* __restrict__ rows,
                                     const int* __restrict__ cols,
                                     const float* __restrict__ vals) {
    int i = blockIdx.x * 256 + threadIdx.x;
    if (i < E_TOT) {
        int r = rows[i];
        int pos = g_rowptr[r] + atomicAdd(&g_cur[r], 1);
        g_edges[pos] = make_int2(cols[i], __float_as_int(vals[i]));
    }
}

// ---------------- fp16 conversions ----------------
// converts rows [base, base+count) of the concatenated (x|motif) matrix
__global__ void convertA_kernel(const float* __restrict__ x,
                                const float* __restrict__ motif,
                                __half* __restrict__ out,
                                int base, int count) {
    int idx = blockIdx.x * 256 + threadIdx.x;      // count*128 threads
    if (idx >= count * 128) return;
    int m  = base + (idx >> 7);
    int kq = (idx & 127) << 2;
    const float* src = (m < N_XROWS)
        ? x + (size_t)m * 512 + kq
        : motif + (size_t)(m - N_XROWS) * 512 + kq;
    float4 v = *(const float4*)src;
    *(uint64_t*)(out + (size_t)m * 512 + kq) =
        pack4h(__float2half_rn(v.x), __float2half_rn(v.y),
               __float2half_rn(v.z), __float2half_rn(v.w));
}

// B [K,N=256] fp32 -> out [n][k] fp16 (B^T, K-major, stride K)
__global__ void convertB_kernel(const float* __restrict__ B, int K,
                                __half* __restrict__ out) {
    int idx = blockIdx.x * 256 + threadIdx.x;    // K*256 threads
    if (idx >= K * 256) return;
    int k = idx >> 8;
    int n = idx & 255;
    out[(size_t)n * K + k] = __float2half_rn(B[idx]);
}

// ---------------- HMMA GEMM: C[M,256] = A16 @ B16^T (1 pass) ----
// CTA tile 64x256 (full N), BK=32, 8 warps as 2(M) x 4(N), warp tile 32x64.
// 3-stage cp.async pipeline, 2 CTAs/SM, fp16 epilogue.
#define SA 40                               // padded SMEM row stride (halfs)
#define STAGE_ELEMS ((64 + 256) * SA)       // A tile + B tile (12800 halfs)
#define GEMM_SMEM   (3 * STAGE_ELEMS * 2)   // 76800 bytes

__global__ void __launch_bounds__(256, 2)
hmma_gemm_kernel(const __half* __restrict__ A,
                 const __half* __restrict__ B1,
                 __half* __restrict__ C, int K, int M) {
    extern __shared__ __half sm[];
    const int t    = threadIdx.x;
    const int lane = t & 31, wid = t >> 5;
    const int wm   = wid & 1, wn = wid >> 1;   // 2 x 4 warp grid
    const int gid  = lane >> 2, tid4 = lane & 3;
    const int row0 = blockIdx.x * 64;
    const int CC = K >> 5;            // 32-wide chunks, single pass

    float acc[2][8][4];
    #pragma unroll
    for (int mi = 0; mi < 2; mi++)
        #pragma unroll
        for (int ni = 0; ni < 8; ni++)
            #pragma unroll
            for (int q = 0; q < 4; q++) acc[mi][ni][q] = 0.f;

    auto load_chunk = [&](int stage, int koff) {
        __half* s  = sm + stage * STAGE_ELEMS;
        __half* sB = s + 64 * SA;
        {                                      // A: 64 rows x 32 halfs
            int r = t >> 2, q = t & 3;
            cp_async16(smem_u32(s + r * SA + q * 8),
                       A + (size_t)(row0 + r) * K + koff + q * 8);
        }
        #pragma unroll
        for (int j = 0; j < 4; j++) {          // B: 256 rows x 32 halfs
            int u = j * 256 + t;
            int r = u >> 2, q = u & 3;
            cp_async16(smem_u32(sB + r * SA + q * 8),
                       B1 + (size_t)r * K + koff + q * 8);
        }
        CP_COMMIT();
    };

    load_chunk(0, 0);
    load_chunk(1, 32);

    for (int c = 0; c < CC; c++) {
        if (c < CC - 1) CP_WAIT(1); else CP_WAIT(0);
        __syncthreads();
        if (c + 2 < CC) load_chunk((c + 2) % 3, (c + 2) << 5);
        const __half* s  = sm + (c % 3) * STAGE_ELEMS;
        const __half* sB = s + 64 * SA;
        #pragma unroll
        for (int ks = 0; ks < 2; ks++) {
            uint32_t a[2][4], b[8][2];
            const int kc = ks * 16 + tid4 * 2;
            #pragma unroll
            for (int mi = 0; mi < 2; mi++) {
                int r0 = wm * 32 + mi * 16 + gid;
                a[mi][0] = *(const uint32_t*)(s + (size_t)r0 * SA + kc);
                a[mi][1] = *(const uint32_t*)(s + (size_t)(r0 + 8) * SA + kc);
                a[mi][2] = *(const uint32_t*)(s + (size_t)r0 * SA + kc + 8);
                a[mi][3] = *(const uint32_t*)(s + (size_t)(r0 + 8) * SA + kc + 8);
            }
            #pragma unroll
            for (int ni = 0; ni < 8; ni++) {
                int n0 = wn * 64 + ni * 8 + gid;
                b[ni][0] = *(const uint32_t*)(sB + (size_t)n0 * SA + kc);
                b[ni][1] = *(const uint32_t*)(sB + (size_t)n0 * SA + kc + 8);
            }
            #pragma unroll
            for (int mi = 0; mi < 2; mi++)
                #pragma unroll
                for (int ni = 0; ni < 8; ni++)
                    mma16816(acc[mi][ni], a[mi], b[ni]);
        }
    }

    // epilogue -> fp16
    #pragma unroll
    for (int mi = 0; mi < 2; mi++) {
        int r = row0 + wm * 32 + mi * 16 + gid;
        #pragma unroll
        for (int ni = 0; ni < 8; ni++) {
            int cidx = wn * 64 + ni * 8 + tid4 * 2;
            if (r < M)
                *(__half2*)(C + (size_t)r * 256 + cidx) =
                    __floats2half2_rn(acc[mi][ni][0], acc[mi][ni][1]);
            if (r + 8 < M)
                *(__half2*)(C + (size_t)(r + 8) * 256 + cidx) =
                    __floats2half2_rn(acc[mi][ni][2], acc[mi][ni][3]);
        }
    }
}

// ---------------- SpMM: warp-per-row, LDG.128 gathers ----------------
__device__ __forceinline__ void fma8(float* acc, float v, uint4 raw) {
    float2 f0 = __half22float2(*(__half2*)&raw.x);
    float2 f1 = __half22float2(*(__half2*)&raw.y);
    float2 f2 = __half22float2(*(__half2*)&raw.z);
    float2 f3 = __half22float2(*(__half2*)&raw.w);
    acc[0] = fmaf(v, f0.x, acc[0]);
    acc[1] = fmaf(v, f0.y, acc[1]);
    acc[2] = fmaf(v, f1.x, acc[2]);
    acc[3] = fmaf(v, f1.y, acc[3]);
    acc[4] = fmaf(v, f2.x, acc[4]);
    acc[5] = fmaf(v, f2.y, acc[5]);
    acc[6] = fmaf(v, f3.x, acc[6]);
    acc[7] = fmaf(v, f3.y, acc[7]);
}

__device__ __forceinline__ void spmm_row_w(const uint4* __restrict__ sup4,
                                           int row, int lane, float* acc) {
    int s = g_rowptr[row];
    int e = g_rowptr[row + 1];
    float acc1[8];
    #pragma unroll
    for (int q = 0; q < 8; q++) { acc[q] = 0.f; acc1[q] = 0.f; }
    int i = s;
    for (; i + 4 <= e; i += 4) {
        int2 e0 = __ldg(&g_edges[i]);
        int2 e1 = __ldg(&g_edges[i + 1]);
        int2 e2 = __ldg(&g_edges[i + 2]);
        int2 e3 = __ldg(&g_edges[i + 3]);
        uint4 r0 = __ldg(&sup4[(size_t)e0.x * 32 + lane]);
        uint4 r1 = __ldg(&sup4[(size_t)e1.x * 32 + lane]);
        uint4 r2 = __ldg(&sup4[(size_t)e2.x * 32 + lane]);
        uint4 r3 = __ldg(&sup4[(size_t)e3.x * 32 + lane]);
        fma8(acc,  __int_as_float(e0.y), r0);
        fma8(acc1, __int_as_float(e1.y), r1);
        fma8(acc,  __int_as_float(e2.y), r2);
        fma8(acc1, __int_as_float(e3.y), r3);
    }
    for (; i < e; i++) {
        int2 ed = __ldg(&g_edges[i]);
        uint4 r0 = __ldg(&sup4[(size_t)ed.x * 32 + lane]);
        fma8(acc, __int_as_float(ed.y), r0);
    }
    #pragma unroll
    for (int q = 0; q < 8; q++) acc[q] += acc1[q];
}

// writes next layer's fp16 A operand (stride 256)
__global__ void __launch_bounds__(256)
spmm_h16_kernel(const uint4* __restrict__ sup4,
                const float4* __restrict__ bias,
                __half* __restrict__ a_next, int nrows) {
    const int row  = blockIdx.x * 8 + (threadIdx.x >> 5);
    const int lane = threadIdx.x & 31;
    if (row >= nrows) return;
    float acc[8];
    spmm_row_w(sup4, row, lane, acc);
    float4 b0 = __ldg(&bias[lane * 2]);
    float4 b1 = __ldg(&bias[lane * 2 + 1]);
    float v0 = fmaxf(acc[0] + b0.x, 0.f), v1 = fmaxf(acc[1] + b0.y, 0.f);
    float v2 = fmaxf(acc[2] + b0.z, 0.f), v3 = fmaxf(acc[3] + b0.w, 0.f);
    float v4 = fmaxf(acc[4] + b1.x, 0.f), v5 = fmaxf(acc[5] + b1.y, 0.f);
    float v6 = fmaxf(acc[6] + b1.z, 0.f), v7 = fmaxf(acc[7] + b1.w, 0.f);
    __half2 h0 = __floats2half2_rn(v0, v1);
    __half2 h1 = __floats2half2_rn(v2, v3);
    __half2 h2 = __floats2half2_rn(v4, v5);
    __half2 h3 = __floats2half2_rn(v6, v7);
    uint4 o;
    o.x = *(uint32_t*)&h0; o.y = *(uint32_t*)&h1;
    o.z = *(uint32_t*)&h2; o.w = *(uint32_t*)&h3;
    *(uint4*)(a_next + (size_t)row * 256 + lane * 8) = o;
}

// Layer-3 SpMM fused with the output permutation: rows < N_XROWS,
// writes relu(agg + b) directly at out[pos[row]].
__global__ void __launch_bounds__(256)
spmm_out_kernel(const uint4* __restrict__ sup4,
                const float4* __restrict__ bias,
                const int* __restrict__ pos,
                float4* __restrict__ out, int nrows) {
    const int row  = blockIdx.x * 8 + (threadIdx.x >> 5);
    const int lane = threadIdx.x & 31;
    if (row >= nrows) return;
    float acc[8];
    spmm_row_w(sup4, row, lane, acc);
    float4 b0 = __ldg(&bias[lane * 2]);
    float4 b1 = __ldg(&bias[lane * 2 + 1]);
    float4 o0, o1;
    o0.x = fmaxf(acc[0] + b0.x, 0.f); o0.y = fmaxf(acc[1] + b0.y, 0.f);
    o0.z = fmaxf(acc[2] + b0.z, 0.f); o0.w = fmaxf(acc[3] + b0.w, 0.f);
    o1.x = fmaxf(acc[4] + b1.x, 0.f); o1.y = fmaxf(acc[5] + b1.y, 0.f);
    o1.z = fmaxf(acc[6] + b1.z, 0.f); o1.w = fmaxf(acc[7] + b1.w, 0.f);
    size_t base = (size_t)__ldg(&pos[row]) * 64 + lane * 2;
    out[base]     = o0;
    out[base + 1] = o1;
}

// ---------------- output zero ----------------
__global__ void zero_out_kernel(float4* __restrict__ out, int n4) {
    int i = blockIdx.x * 256 + threadIdx.x;
    if (i < n4) out[i] = make_float4(0.f, 0.f, 0.f, 0.f);
}

// ---------------- launch ----------------
extern "C" void kernel_launch(void* const* d_in, const int* in_sizes, int n_in,
                              void* d_out, int out_size) {
    const float* x     = (const float*)d_in[0];
    const float* motif = (const float*)d_in[1];
    const int*   rows  = (const int*)d_in[2];
    const int*   cols  = (const int*)d_in[3];
    const float* vals  = (const float*)d_in[4];
    const int*   pos   = (const int*)d_in[5];
    int wi = 6;
    if (n_in >= 13 && in_sizes[6] == 1) wi = 7;
    const float* w1 = (const float*)d_in[wi + 0];
    const float* b1 = (const float*)d_in[wi + 1];
    const float* w2 = (const float*)d_in[wi + 2];
    const float* b2 = (const float*)d_in[wi + 3];
    const float* w3 = (const float*)d_in[wi + 4];
    const float* b3 = (const float*)d_in[wi + 5];

    __half *support, *a, *bt1, *bt2, *bt3;
    cudaGetSymbolAddress((void**)&support, g_support);
    cudaGetSymbolAddress((void**)&a, g_a);
    cudaGetSymbolAddress((void**)&bt1, g_b1);
    cudaGetSymbolAddress((void**)&bt2, g_b2);
    cudaGetSymbolAddress((void**)&bt3, g_b3);

    cudaFuncSetAttribute(hmma_gemm_kernel,
                         cudaFuncAttributeMaxDynamicSharedMemorySize, GEMM_SMEM);

    // ONE side stream (two-wide graphs passed teardown in R9/R11; the
    // three-wide R10 graph leaked upload-pool memory). Created per call,
    // intentionally not destroyed mid-capture.
    cudaStream_t s2;
    cudaStreamCreateWithFlags(&s2, cudaStreamNonBlocking);
    cudaEvent_t evFork, evA1, evCsr, evZero;
    cudaEventCreateWithFlags(&evFork, cudaEventDisableTiming);
    cudaEventCreateWithFlags(&evA1,   cudaEventDisableTiming);
    cudaEventCreateWithFlags(&evCsr,  cudaEventDisableTiming);
    cudaEventCreateWithFlags(&evZero, cudaEventDisableTiming);

    cudaEventRecord(evFork, 0);
    cudaStreamWaitEvent(s2, evFork, 0);

    const int gemm_half = SPLIT / 64;        // 469
    const int gemm_full = M_PAD / 64;        // 938
    const int spmm_grid = (N_TOT + 7) / 8;
    const int spmo_grid = (N_XROWS + 7) / 8;
    int n4 = out_size / 4;

    // --- side chain (s2): A half-1 convert, packed CSR build, zero out ---
    convertA_kernel<<<(H1ROWS * 128 + 255) / 256, 256, 0, s2>>>(x, motif, a,
                                                                SPLIT, H1ROWS);
    cudaEventRecord(evA1, s2);
    zero_cnt_kernel<<<(N_TOT + 255) / 256, 256, 0, s2>>>();
    hist_kernel<<<E_TOT / 256, 256, 0, s2>>>(rows);
    scan_kernel<<<1, 1024, 0, s2>>>();
    scatter_edges_kernel<<<E_TOT / 256, 256, 0, s2>>>(rows, cols, vals);
    cudaEventRecord(evCsr, s2);
    zero_out_kernel<<<(n4 + 255) / 256, 256, 0, s2>>>((float4*)d_out, n4);
    cudaEventRecord(evZero, s2);

    // --- main chain: weights + A half-0 + layer-1 GEMM (split halves) ---
    convertB_kernel<<<512, 256>>>(w1, 512, bt1);
    convertB_kernel<<<256, 256>>>(w2, 256, bt2);
    convertB_kernel<<<256, 256>>>(w3, 256, bt3);
    convertA_kernel<<<(SPLIT * 128) / 256, 256>>>(x, motif, a, 0, SPLIT);
    hmma_gemm_kernel<<<gemm_half, 256, GEMM_SMEM>>>(a, bt1, support, 512, SPLIT);
    cudaStreamWaitEvent(0, evA1, 0);
    hmma_gemm_kernel<<<gemm_half, 256, GEMM_SMEM>>>(
        a + (size_t)SPLIT * 512, bt1, support + (size_t)SPLIT * 256,
        512, H1ROWS);

    // join: layer-1 SpMM needs the packed CSR
    cudaStreamWaitEvent(0, evCsr, 0);
    spmm_h16_kernel<<<spmm_grid, 256>>>((const uint4*)support,
                                        (const float4*)b1, a, N_TOT);

    // --- layer 2 (K=256) ---
    hmma_gemm_kernel<<<gemm_full, 256, GEMM_SMEM>>>(a, bt2, support, 256, N_TOT);
    spmm_h16_kernel<<<spmm_grid, 256>>>((const uint4*)support,
                                        (const float4*)b2, a, N_TOT);

    // --- layer 3 (K=256): SpMM fused with output scatter ---
    hmma_gemm_kernel<<<gemm_full, 256, GEMM_SMEM>>>(a, bt3, support, 256, N_TOT);
    cudaStreamWaitEvent(0, evZero, 0);
    spmm_out_kernel<<<spmo_grid, 256>>>((const uint4*)support,
                                        (const float4*)b3, pos,
                                        (float4*)d_out, N_XROWS);
}

// round 13
// speedup vs baseline: 1.1493x; 1.0115x over previous
#include <cuda_runtime.h>
#include <cuda_fp16.h>
#include <cstdint>

#define N_XROWS   50000
#define N_MOTIF   10000
#define N_TOT     60000
#define E_TOT     1920000
#define NHID      256
#define PAD_N     65536
#define M_PAD     60032          // 938 * 64
#define SPLIT     30016          // 469 * 64
#define H1ROWS    (N_TOT - SPLIT)
#define NB_SCAN   ((N_TOT + 1023) / 1024)   // 59

// ---------------- device scratch (no allocs allowed) ----------------
__device__ int   g_cnt[N_TOT];
__device__ int   g_cur[N_TOT];
__device__ int   g_rowptr[N_TOT + 1];
__device__ int   g_bsum[64];
__device__ int2  g_edges[E_TOT];
__device__ __half g_support[(size_t)N_TOT * NHID];     // fp16 support
__device__ __half g_a[(size_t)M_PAD * 512];            // A operand, fp16
__device__ __half g_b1[256 * 512];                     // W1^T fp16, K-major
__device__ __half g_b2[256 * 256];                     // W2^T fp16
__device__ __half g_b3[256 * 256];                     // W3^T fp16

// ================= helpers =================
__device__ __forceinline__ uint32_t smem_u32(const void* p) {
    uint32_t a;
    asm("{ .reg .u64 t; cvta.to.shared.u64 t, %1; cvt.u32.u64 %0, t; }"
        : "=r"(a) : "l"(p));
    return a;
}
__device__ __forceinline__ void cp_async16(uint32_t dst, const void* src) {
    asm volatile("cp.async.cg.shared.global [%0], [%1], 16;"
                 :: "r"(dst), "l"(__cvta_generic_to_global(src)) : "memory");
}
#define CP_COMMIT() asm volatile("cp.async.commit_group;" ::: "memory")
#define CP_WAIT(n)  asm volatile("cp.async.wait_group %0;" :: "n"(n) : "memory")

__device__ __forceinline__ void mma16816(float* d, const uint32_t* a,
                                         const uint32_t* b) {
    asm volatile(
        "mma.sync.aligned.m16n8k16.row.col.f32.f16.f16.f32 "
        "{%0,%1,%2,%3}, {%4,%5,%6,%7}, {%8,%9}, {%0,%1,%2,%3};"
        : "+f"(d[0]), "+f"(d[1]), "+f"(d[2]), "+f"(d[3])
        : "r"(a[0]), "r"(a[1]), "r"(a[2]), "r"(a[3]), "r"(b[0]), "r"(b[1]));
}

__device__ __forceinline__ uint64_t pack4h(__half a, __half b, __half c, __half d) {
    __half2 p0 = __halves2half2(a, b);
    __half2 p1 = __halves2half2(c, d);
    uint32_t u0 = *(uint32_t*)&p0;
    uint32_t u1 = *(uint32_t*)&p1;
    return (uint64_t)u0 | ((uint64_t)u1 << 32);
}

// ---------------- CSR build (packed, parallel scan) ----------------
__global__ void zero_cnt_kernel() {
    int i = blockIdx.x * 256 + threadIdx.x;
    if (i < N_TOT) { g_cnt[i] = 0; g_cur[i] = 0; }
}
__global__ void hist_kernel(const int* __restrict__ rows) {
    int i = blockIdx.x * 256 + threadIdx.x;
    if (i < E_TOT) atomicAdd(&g_cnt[rows[i]], 1);
}

// block-level exclusive scan over 1024 elements; writes per-block totals
__global__ void scan_local_kernel() {
    __shared__ int wsum[32];
    const int tid = threadIdx.x;
    const int lane = tid & 31, wid = tid >> 5;
    int i = blockIdx.x * 1024 + tid;
    int x = (i < N_TOT) ? g_cnt[i] : 0;
    int v = x;
    #pragma unroll
    for (int off = 1; off < 32; off <<= 1) {
        int u = __shfl_up_sync(0xffffffffu, v, off);
        if (lane >= off) v += u;
    }
    if (lane == 31) wsum[wid] = v;
    __syncthreads();
    if (wid == 0) {
        int w = wsum[lane];
        #pragma unroll
        for (int off = 1; off < 32; off <<= 1) {
            int u = __shfl_up_sync(0xffffffffu, w, off);
            if (lane >= off) w += u;
        }
        wsum[lane] = w;
    }
    __syncthreads();
    int warp_prefix = (wid == 0) ? 0 : wsum[wid - 1];
    int excl = warp_prefix + v - x;
    if (i < N_TOT) g_rowptr[i] = excl;
    if (tid == 1023) g_bsum[blockIdx.x] = excl + x;
}

// single 64-thread block: exclusive scan of the NB_SCAN block sums
__global__ void scan_sums_kernel() {
    __shared__ int w0sum;
    const int tid = threadIdx.x;           // 64 threads, 2 warps
    const int lane = tid & 31, wid = tid >> 5;
    int x = (tid < NB_SCAN) ? g_bsum[tid] : 0;
    int v = x;
    #pragma unroll
    for (int off = 1; off < 32; off <<= 1) {
        int u = __shfl_up_sync(0xffffffffu, v, off);
        if (lane >= off) v += u;
    }
    if (wid == 0 && lane == 31) w0sum = v;
    __syncthreads();
    int excl = v - x + ((wid == 1) ? w0sum : 0);
    if (tid < NB_SCAN) g_bsum[tid] = excl;
    if (tid == 0) g_rowptr[N_TOT] = E_TOT;  // total = all edges, exact
}

__global__ void scan_add_kernel() {
    int i = blockIdx.x * 1024 + threadIdx.x;
    if (i < N_TOT) g_rowptr[i] += g_bsum[blockIdx.x];
}

__global__ void scatter_edges_kernel(const int* __restrict__ rows,
                                     const int* __restrict__ cols,
                                     const float* __restrict__ vals) {
    int i = blockIdx.x * 256 + threadIdx.x;
    if (i < E_TOT) {
        int r = rows[i];
        int pos = g_rowptr[r] + atomicAdd(&g_cur[r], 1);
        g_edges[pos] = make_int2(cols[i], __float_as_int(vals[i]));
    }
}

// ---------------- fp16 conversions ----------------
// converts rows [base, base+count) of the concatenated (x|motif) matrix
__global__ void convertA_kernel(const float* __restrict__ x,
                                const float* __restrict__ motif,
                                __half* __restrict__ out,
                                int base, int count) {
    int idx = blockIdx.x * 256 + threadIdx.x;      // count*128 threads
    if (idx >= count * 128) return;
    int m  = base + (idx >> 7);
    int kq = (idx & 127) << 2;
    const float* src = (m < N_XROWS)
        ? x + (size_t)m * 512 + kq
        : motif + (size_t)(m - N_XROWS) * 512 + kq;
    float4 v = *(const float4*)src;
    *(uint64_t*)(out + (size_t)m * 512 + kq) =
        pack4h(__float2half_rn(v.x), __float2half_rn(v.y),
               __float2half_rn(v.z), __float2half_rn(v.w));
}

// B [K,N=256] fp32 -> out [n][k] fp16 (B^T, K-major, stride K)
__global__ void convertB_kernel(const float* __restrict__ B, int K,
                                __half* __restrict__ out) {
    int idx = blockIdx.x * 256 + threadIdx.x;    // K*256 threads
    if (idx >= K * 256) return;
    int k = idx >> 8;
    int n = idx & 255;
    out[(size_t)n * K + k] = __float2half_rn(B[idx]);
}

// ---------------- HMMA GEMM: C[M,256] = A16 @ B16^T (1 pass) ----
// CTA tile 64x256 (full N), BK=32, 8 warps as 2(M) x 4(N), warp tile 32x64.
// 3-stage cp.async pipeline, 2 CTAs/SM, fp16 epilogue.
#define SA 40                               // padded SMEM row stride (halfs)
#define STAGE_ELEMS ((64 + 256) * SA)       // A tile + B tile (12800 halfs)
#define GEMM_SMEM   (3 * STAGE_ELEMS * 2)   // 76800 bytes

__global__ void __launch_bounds__(256, 2)
hmma_gemm_kernel(const __half* __restrict__ A,
                 const __half* __restrict__ B1,
                 __half* __restrict__ C, int K, int M) {
    extern __shared__ __half sm[];
    const int t    = threadIdx.x;
    const int lane = t & 31, wid = t >> 5;
    const int wm   = wid & 1, wn = wid >> 1;   // 2 x 4 warp grid
    const int gid  = lane >> 2, tid4 = lane & 3;
    const int row0 = blockIdx.x * 64;
    const int CC = K >> 5;            // 32-wide chunks, single pass

    float acc[2][8][4];
    #pragma unroll
    for (int mi = 0; mi < 2; mi++)
        #pragma unroll
        for (int ni = 0; ni < 8; ni++)
            #pragma unroll
            for (int q = 0; q < 4; q++) acc[mi][ni][q] = 0.f;

    auto load_chunk = [&](int stage, int koff) {
        __half* s  = sm + stage * STAGE_ELEMS;
        __half* sB = s + 64 * SA;
        {                                      // A: 64 rows x 32 halfs
            int r = t >> 2, q = t & 3;
            cp_async16(smem_u32(s + r * SA + q * 8),
                       A + (size_t)(row0 + r) * K + koff + q * 8);
        }
        #pragma unroll
        for (int j = 0; j < 4; j++) {          // B: 256 rows x 32 halfs
            int u = j * 256 + t;
            int r = u >> 2, q = u & 3;
            cp_async16(smem_u32(sB + r * SA + q * 8),
                       B1 + (size_t)r * K + koff + q * 8);
        }
        CP_COMMIT();
    };

    load_chunk(0, 0);
    load_chunk(1, 32);

    for (int c = 0; c < CC; c++) {
        if (c < CC - 1) CP_WAIT(1); else CP_WAIT(0);
        __syncthreads();
        if (c + 2 < CC) load_chunk((c + 2) % 3, (c + 2) << 5);
        const __half* s  = sm + (c % 3) * STAGE_ELEMS;
        const __half* sB = s + 64 * SA;
        #pragma unroll
        for (int ks = 0; ks < 2; ks++) {
            uint32_t a[2][4], b[8][2];
            const int kc = ks * 16 + tid4 * 2;
            #pragma unroll
            for (int mi = 0; mi < 2; mi++) {
                int r0 = wm * 32 + mi * 16 + gid;
                a[mi][0] = *(const uint32_t*)(s + (size_t)r0 * SA + kc);
                a[mi][1] = *(const uint32_t*)(s + (size_t)(r0 + 8) * SA + kc);
                a[mi][2] = *(const uint32_t*)(s + (size_t)r0 * SA + kc + 8);
                a[mi][3] = *(const uint32_t*)(s + (size_t)(r0 + 8) * SA + kc + 8);
            }
            #pragma unroll
            for (int ni = 0; ni < 8; ni++) {
                int n0 = wn * 64 + ni * 8 + gid;
                b[ni][0] = *(const uint32_t*)(sB + (size_t)n0 * SA + kc);
                b[ni][1] = *(const uint32_t*)(sB + (size_t)n0 * SA + kc + 8);
            }
            #pragma unroll
            for (int mi = 0; mi < 2; mi++)
                #pragma unroll
                for (int ni = 0; ni < 8; ni++)
                    mma16816(acc[mi][ni], a[mi], b[ni]);
        }
    }

    // epilogue -> fp16
    #pragma unroll
    for (int mi = 0; mi < 2; mi++) {
        int r = row0 + wm * 32 + mi * 16 + gid;
        #pragma unroll
        for (int ni = 0; ni < 8; ni++) {
            int cidx = wn * 64 + ni * 8 + tid4 * 2;
            if (r < M)
                *(__half2*)(C + (size_t)r * 256 + cidx) =
                    __floats2half2_rn(acc[mi][ni][0], acc[mi][ni][1]);
            if (r + 8 < M)
                *(__half2*)(C + (size_t)(r + 8) * 256 + cidx) =
                    __floats2half2_rn(acc[mi][ni][2], acc[mi][ni][3]);
        }
    }
}

// ---------------- SpMM: warp-per-row, LDG.128 gathers ----------------
__device__ __forceinline__ void fma8(float* acc, float v, uint4 raw) {
    float2 f0 = __half22float2(*(__half2*)&raw.x);
    float2 f1 = __half22float2(*(__half2*)&raw.y);
    float2 f2 = __half22float2(*(__half2*)&raw.z);
    float2 f3 = __half22float2(*(__half2*)&raw.w);
    acc[0] = fmaf(v, f0.x, acc[0]);
    acc[1] = fmaf(v, f0.y, acc[1]);
    acc[2] = fmaf(v, f1.x, acc[2]);
    acc[3] = fmaf(v, f1.y, acc[3]);
    acc[4] = fmaf(v, f2.x, acc[4]);
    acc[5] = fmaf(v, f2.y, acc[5]);
    acc[6] = fmaf(v, f3.x, acc[6]);
    acc[7] = fmaf(v, f3.y, acc[7]);
}

__device__ __forceinline__ void spmm_row_w(const uint4* __restrict__ sup4,
                                           int row, int lane, float* acc) {
    int s = g_rowptr[row];
    int e = g_rowptr[row + 1];
    float acc1[8];
    #pragma unroll
    for (int q = 0; q < 8; q++) { acc[q] = 0.f; acc1[q] = 0.f; }
    int i = s;
    for (; i + 4 <= e; i += 4) {
        int2 e0 = __ldg(&g_edges[i]);
        int2 e1 = __ldg(&g_edges[i + 1]);
        int2 e2 = __ldg(&g_edges[i + 2]);
        int2 e3 = __ldg(&g_edges[i + 3]);
        uint4 r0 = __ldg(&sup4[(size_t)e0.x * 32 + lane]);
        uint4 r1 = __ldg(&sup4[(size_t)e1.x * 32 + lane]);
        uint4 r2 = __ldg(&sup4[(size_t)e2.x * 32 + lane]);
        uint4 r3 = __ldg(&sup4[(size_t)e3.x * 32 + lane]);
        fma8(acc,  __int_as_float(e0.y), r0);
        fma8(acc1, __int_as_float(e1.y), r1);
        fma8(acc,  __int_as_float(e2.y), r2);
        fma8(acc1, __int_as_float(e3.y), r3);
    }
    for (; i < e; i++) {
        int2 ed = __ldg(&g_edges[i]);
        uint4 r0 = __ldg(&sup4[(size_t)ed.x * 32 + lane]);
        fma8(acc, __int_as_float(ed.y), r0);
    }
    #pragma unroll
    for (int q = 0; q < 8; q++) acc[q] += acc1[q];
}

// writes next layer's fp16 A operand (stride 256)
__global__ void __launch_bounds__(256)
spmm_h16_kernel(const uint4* __restrict__ sup4,
                const float4* __restrict__ bias,
                __half* __restrict__ a_next, int nrows) {
    const int row  = blockIdx.x * 8 + (threadIdx.x >> 5);
    const int lane = threadIdx.x & 31;
    if (row >= nrows) return;
    float acc[8];
    spmm_row_w(sup4, row, lane, acc);
    float4 b0 = __ldg(&bias[lane * 2]);
    float4 b1 = __ldg(&bias[lane * 2 + 1]);
    float v0 = fmaxf(acc[0] + b0.x, 0.f), v1 = fmaxf(acc[1] + b0.y, 0.f);
    float v2 = fmaxf(acc[2] + b0.z, 0.f), v3 = fmaxf(acc[3] + b0.w, 0.f);
    float v4 = fmaxf(acc[4] + b1.x, 0.f), v5 = fmaxf(acc[5] + b1.y, 0.f);
    float v6 = fmaxf(acc[6] + b1.z, 0.f), v7 = fmaxf(acc[7] + b1.w, 0.f);
    __half2 h0 = __floats2half2_rn(v0, v1);
    __half2 h1 = __floats2half2_rn(v2, v3);
    __half2 h2 = __floats2half2_rn(v4, v5);
    __half2 h3 = __floats2half2_rn(v6, v7);
    uint4 o;
    o.x = *(uint32_t*)&h0; o.y = *(uint32_t*)&h1;
    o.z = *(uint32_t*)&h2; o.w = *(uint32_t*)&h3;
    *(uint4*)(a_next + (size_t)row * 256 + lane * 8) = o;
}

// Layer-3 SpMM fused with the output permutation: rows < N_XROWS,
// writes relu(agg + b) directly at out[pos[row]].
__global__ void __launch_bounds__(256)
spmm_out_kernel(const uint4* __restrict__ sup4,
                const float4* __restrict__ bias,
                const int* __restrict__ pos,
                float4* __restrict__ out, int nrows) {
    const int row  = blockIdx.x * 8 + (threadIdx.x >> 5);
    const int lane = threadIdx.x & 31;
    if (row >= nrows) return;
    float acc[8];
    spmm_row_w(sup4, row, lane, acc);
    float4 b0 = __ldg(&bias[lane * 2]);
    float4 b1 = __ldg(&bias[lane * 2 + 1]);
    float4 o0, o1;
    o0.x = fmaxf(acc[0] + b0.x, 0.f); o0.y = fmaxf(acc[1] + b0.y, 0.f);
    o0.z = fmaxf(acc[2] + b0.z, 0.f); o0.w = fmaxf(acc[3] + b0.w, 0.f);
    o1.x = fmaxf(acc[4] + b1.x, 0.f); o1.y = fmaxf(acc[5] + b1.y, 0.f);
    o1.z = fmaxf(acc[6] + b1.z, 0.f); o1.w = fmaxf(acc[7] + b1.w, 0.f);
    size_t base = (size_t)__ldg(&pos[row]) * 64 + lane * 2;
    out[base]     = o0;
    out[base + 1] = o1;
}

// ---------------- output zero ----------------
__global__ void zero_out_kernel(float4* __restrict__ out, int n4) {
    int i = blockIdx.x * 256 + threadIdx.x;
    if (i < n4) out[i] = make_float4(0.f, 0.f, 0.f, 0.f);
}

// ---------------- launch ----------------
extern "C" void kernel_launch(void* const* d_in, const int* in_sizes, int n_in,
                              void* d_out, int out_size) {
    const float* x     = (const float*)d_in[0];
    const float* motif = (const float*)d_in[1];
    const int*   rows  = (const int*)d_in[2];
    const int*   cols  = (const int*)d_in[3];
    const float* vals  = (const float*)d_in[4];
    const int*   pos   = (const int*)d_in[5];
    int wi = 6;
    if (n_in >= 13 && in_sizes[6] == 1) wi = 7;
    const float* w1 = (const float*)d_in[wi + 0];
    const float* b1 = (const float*)d_in[wi + 1];
    const float* w2 = (const float*)d_in[wi + 2];
    const float* b2 = (const float*)d_in[wi + 3];
    const float* w3 = (const float*)d_in[wi + 4];
    const float* b3 = (const float*)d_in[wi + 5];

    __half *support, *a, *bt1, *bt2, *bt3;
    cudaGetSymbolAddress((void**)&support, g_support);
    cudaGetSymbolAddress((void**)&a, g_a);
    cudaGetSymbolAddress((void**)&bt1, g_b1);
    cudaGetSymbolAddress((void**)&bt2, g_b2);
    cudaGetSymbolAddress((void**)&bt3, g_b3);

    cudaFuncSetAttribute(hmma_gemm_kernel,
                         cudaFuncAttributeMaxDynamicSharedMemorySize, GEMM_SMEM);

    // ONE side stream (two-wide graphs pass teardown; three-wide leaked).
    // Created per call, intentionally not destroyed mid-capture.
    cudaStream_t s2;
    cudaStreamCreateWithFlags(&s2, cudaStreamNonBlocking);
    cudaEvent_t evFork, evA1, evCsr, evZero;
    cudaEventCreateWithFlags(&evFork, cudaEventDisableTiming);
    cudaEventCreateWithFlags(&evA1,   cudaEventDisableTiming);
    cudaEventCreateWithFlags(&evCsr,  cudaEventDisableTiming);
    cudaEventCreateWithFlags(&evZero, cudaEventDisableTiming);

    cudaEventRecord(evFork, 0);
    cudaStreamWaitEvent(s2, evFork, 0);

    const int gemm_half = SPLIT / 64;        // 469
    const int gemm_full = M_PAD / 64;        // 938
    const int spmm_grid = (N_TOT + 7) / 8;
    const int spmo_grid = (N_XROWS + 7) / 8;
    int n4 = out_size / 4;

    // --- side chain (s2): A half-1 convert, CSR build (parallel scan), zero ---
    convertA_kernel<<<(H1ROWS * 128 + 255) / 256, 256, 0, s2>>>(x, motif, a,
                                                                SPLIT, H1ROWS);
    cudaEventRecord(evA1, s2);
    zero_cnt_kernel<<<(N_TOT + 255) / 256, 256, 0, s2>>>();
    hist_kernel<<<E_TOT / 256, 256, 0, s2>>>(rows);
    scan_local_kernel<<<NB_SCAN, 1024, 0, s2>>>();
    scan_sums_kernel<<<1, 64, 0, s2>>>();
    scan_add_kernel<<<NB_SCAN, 1024, 0, s2>>>();
    scatter_edges_kernel<<<E_TOT / 256, 256, 0, s2>>>(rows, cols, vals);
    cudaEventRecord(evCsr, s2);
    zero_out_kernel<<<(n4 + 255) / 256, 256, 0, s2>>>((float4*)d_out, n4);
    cudaEventRecord(evZero, s2);

    // --- main chain: weights + A half-0 + layer-1 GEMM (split halves) ---
    convertB_kernel<<<512, 256>>>(w1, 512, bt1);
    convertB_kernel<<<256, 256>>>(w2, 256, bt2);
    convertB_kernel<<<256, 256>>>(w3, 256, bt3);
    convertA_kernel<<<(SPLIT * 128) / 256, 256>>>(x, motif, a, 0, SPLIT);
    hmma_gemm_kernel<<<gemm_half, 256, GEMM_SMEM>>>(a, bt1, support, 512, SPLIT);
    cudaStreamWaitEvent(0, evA1, 0);
    hmma_gemm_kernel<<<gemm_half, 256, GEMM_SMEM>>>(
        a + (size_t)SPLIT * 512, bt1, support + (size_t)SPLIT * 256,
        512, H1ROWS);

    // join: layer-1 SpMM needs the packed CSR
    cudaStreamWaitEvent(0, evCsr, 0);
    spmm_h16_kernel<<<spmm_grid, 256>>>((const uint4*)support,
                                        (const float4*)b1, a, N_TOT);

    // --- layer 2 (K=256) ---
    hmma_gemm_kernel<<<gemm_full, 256, GEMM_SMEM>>>(a, bt2, support, 256, N_TOT);
    spmm_h16_kernel<<<spmm_grid, 256>>>((const uint4*)support,
                                        (const float4*)b2, a, N_TOT);

    // --- layer 3 (K=256): SpMM fused with output scatter ---
    hmma_gemm_kernel<<<gemm_full, 256, GEMM_SMEM>>>(a, bt3, support, 256, N_TOT);
    cudaStreamWaitEvent(0, evZero, 0);
    spmm_out_kernel<<<spmo_grid, 256>>>((const uint4*)support,
                                        (const float4*)b3, pos,
                                        (float4*)d_out, N_XROWS);
}

// round 14
// speedup vs baseline: 1.1579x; 1.0075x over previous
#include <cuda_runtime.h>
#include <cuda_fp16.h>
#include <cstdint>

#define N_XROWS   50000
#define N_MOTIF   10000
#define N_TOT     60000
#define E_TOT     1920000
#define NHID      256
#define PAD_N     65536
#define M_PAD     60032          // 938 * 64
#define NB_SCAN   ((N_TOT + 1023) / 1024)   // 59

// ---------------- device scratch (no allocs allowed) ----------------
__device__ int   g_cnt[N_TOT];
__device__ int   g_cur[N_TOT];
__device__ int   g_rowptr[N_TOT + 1];
__device__ int   g_bsum[64];
__device__ int2  g_edges[E_TOT];
__device__ __half g_support[(size_t)N_TOT * NHID];     // fp16 support
__device__ __half g_a[(size_t)M_PAD * 512];            // A operand, fp16
__device__ __half g_b1[256 * 512];                     // W1^T fp16, K-major
__device__ __half g_b2[256 * 256];                     // W2^T fp16
__device__ __half g_b3[256 * 256];                     // W3^T fp16

// ================= helpers =================
__device__ __forceinline__ uint32_t smem_u32(const void* p) {
    uint32_t a;
    asm("{ .reg .u64 t; cvta.to.shared.u64 t, %1; cvt.u32.u64 %0, t; }"
        : "=r"(a) : "l"(p));
    return a;
}
__device__ __forceinline__ void cp_async16(uint32_t dst, const void* src) {
    asm volatile("cp.async.cg.shared.global [%0], [%1], 16;"
                 :: "r"(dst), "l"(__cvta_generic_to_global(src)) : "memory");
}
#define CP_COMMIT() asm volatile("cp.async.commit_group;" ::: "memory")
#define CP_WAIT(n)  asm volatile("cp.async.wait_group %0;" :: "n"(n) : "memory")

__device__ __forceinline__ void mma16816(float* d, const uint32_t* a,
                                         const uint32_t* b) {
    asm volatile(
        "mma.sync.aligned.m16n8k16.row.col.f32.f16.f16.f32 "
        "{%0,%1,%2,%3}, {%4,%5,%6,%7}, {%8,%9}, {%0,%1,%2,%3};"
        : "+f"(d[0]), "+f"(d[1]), "+f"(d[2]), "+f"(d[3])
        : "r"(a[0]), "r"(a[1]), "r"(a[2]), "r"(a[3]), "r"(b[0]), "r"(b[1]));
}

__device__ __forceinline__ uint64_t pack4h(__half a, __half b, __half c, __half d) {
    __half2 p0 = __halves2half2(a, b);
    __half2 p1 = __halves2half2(c, d);
    uint32_t u0 = *(uint32_t*)&p0;
    uint32_t u1 = *(uint32_t*)&p1;
    return (uint64_t)u0 | ((uint64_t)u1 << 32);
}

// ---------------- CSR build (packed, parallel scan) ----------------
__global__ void zero_cnt_kernel() {
    int i = blockIdx.x * 256 + threadIdx.x;
    if (i < N_TOT) { g_cnt[i] = 0; g_cur[i] = 0; }
}
__global__ void hist_kernel(const int* __restrict__ rows) {
    int i = blockIdx.x * 256 + threadIdx.x;
    if (i < E_TOT) atomicAdd(&g_cnt[rows[i]], 1);
}

// block-level exclusive scan over 1024 elements; writes per-block totals
__global__ void scan_local_kernel() {
    __shared__ int wsum[32];
    const int tid = threadIdx.x;
    const int lane = tid & 31, wid = tid >> 5;
    int i = blockIdx.x * 1024 + tid;
    int x = (i < N_TOT) ? g_cnt[i] : 0;
    int v = x;
    #pragma unroll
    for (int off = 1; off < 32; off <<= 1) {
        int u = __shfl_up_sync(0xffffffffu, v, off);
        if (lane >= off) v += u;
    }
    if (lane == 31) wsum[wid] = v;
    __syncthreads();
    if (wid == 0) {
        int w = wsum[lane];
        #pragma unroll
        for (int off = 1; off < 32; off <<= 1) {
            int u = __shfl_up_sync(0xffffffffu, w, off);
            if (lane >= off) w += u;
        }
        wsum[lane] = w;
    }
    __syncthreads();
    int warp_prefix = (wid == 0) ? 0 : wsum[wid - 1];
    int excl = warp_prefix + v - x;
    if (i < N_TOT) g_rowptr[i] = excl;
    if (tid == 1023) g_bsum[blockIdx.x] = excl + x;
}

// single 64-thread block: exclusive scan of the NB_SCAN block sums
__global__ void scan_sums_kernel() {
    __shared__ int w0sum;
    const int tid = threadIdx.x;           // 64 threads, 2 warps
    const int lane = tid & 31, wid = tid >> 5;
    int x = (tid < NB_SCAN) ? g_bsum[tid] : 0;
    int v = x;
    #pragma unroll
    for (int off = 1; off < 32; off <<= 1) {
        int u = __shfl_up_sync(0xffffffffu, v, off);
        if (lane >= off) v += u;
    }
    if (wid == 0 && lane == 31) w0sum = v;
    __syncthreads();
    int excl = v - x + ((wid == 1) ? w0sum : 0);
    if (tid < NB_SCAN) g_bsum[tid] = excl;
    if (tid == 0) g_rowptr[N_TOT] = E_TOT;  // total = all edges, exact
}

__global__ void scan_add_kernel() {
    int i = blockIdx.x * 1024 + threadIdx.x;
    if (i < N_TOT) g_rowptr[i] += g_bsum[blockIdx.x];
}

__global__ void scatter_edges_kernel(const int* __restrict__ rows,
                                     const int* __restrict__ cols,
                                     const float* __restrict__ vals) {
    int i = blockIdx.x * 256 + threadIdx.x;
    if (i < E_TOT) {
        int r = rows[i];
        int pos = g_rowptr[r] + atomicAdd(&g_cur[r], 1);
        g_edges[pos] = make_int2(cols[i], __float_as_int(vals[i]));
    }
}

// ---------------- fp16 conversions ----------------
__global__ void convertA_kernel(const float* __restrict__ x,
                                const float* __restrict__ motif,
                                __half* __restrict__ out) {
    int idx = blockIdx.x * 256 + threadIdx.x;      // N_TOT*128 threads
    if (idx >= N_TOT * 128) return;
    int m  = idx >> 7;
    int kq = (idx & 127) << 2;
    const float* src = (m < N_XROWS)
        ? x + (size_t)m * 512 + kq
        : motif + (size_t)(m - N_XROWS) * 512 + kq;
    float4 v = *(const float4*)src;
    *(uint64_t*)(out + (size_t)m * 512 + kq) =
        pack4h(__float2half_rn(v.x), __float2half_rn(v.y),
               __float2half_rn(v.z), __float2half_rn(v.w));
}

// B [K,N=256] fp32 -> out [n][k] fp16 (B^T, K-major, stride K)
__global__ void convertB_kernel(const float* __restrict__ B, int K,
                                __half* __restrict__ out) {
    int idx = blockIdx.x * 256 + threadIdx.x;    // K*256 threads
    if (idx >= K * 256) return;
    int k = idx >> 8;
    int n = idx & 255;
    out[(size_t)n * K + k] = __float2half_rn(B[idx]);
}

// ---------------- HMMA GEMM: C[M,256] = A16 @ B16^T (1 pass) ----
// CTA tile 64x256 (full N), BK=32, 8 warps as 2(M) x 4(N), warp tile 32x64.
// 3-stage cp.async pipeline, 2 CTAs/SM, fp16 epilogue.
#define SA 40                               // padded SMEM row stride (halfs)
#define STAGE_ELEMS ((64 + 256) * SA)       // A tile + B tile (12800 halfs)
#define GEMM_SMEM   (3 * STAGE_ELEMS * 2)   // 76800 bytes

__global__ void __launch_bounds__(256, 2)
hmma_gemm_kernel(const __half* __restrict__ A,
                 const __half* __restrict__ B1,
                 __half* __restrict__ C, int K, int M) {
    extern __shared__ __half sm[];
    const int t    = threadIdx.x;
    const int lane = t & 31, wid = t >> 5;
    const int wm   = wid & 1, wn = wid >> 1;   // 2 x 4 warp grid
    const int gid  = lane >> 2, tid4 = lane & 3;
    const int row0 = blockIdx.x * 64;
    const int CC = K >> 5;            // 32-wide chunks, single pass

    float acc[2][8][4];
    #pragma unroll
    for (int mi = 0; mi < 2; mi++)
        #pragma unroll
        for (int ni = 0; ni < 8; ni++)
            #pragma unroll
            for (int q = 0; q < 4; q++) acc[mi][ni][q] = 0.f;

    auto load_chunk = [&](int stage, int koff) {
        __half* s  = sm + stage * STAGE_ELEMS;
        __half* sB = s + 64 * SA;
        {                                      // A: 64 rows x 32 halfs
            int r = t >> 2, q = t & 3;
            cp_async16(smem_u32(s + r * SA + q * 8),
                       A + (size_t)(row0 + r) * K + koff + q * 8);
        }
        #pragma unroll
        for (int j = 0; j < 4; j++) {          // B: 256 rows x 32 halfs
            int u = j * 256 + t;
            int r = u >> 2, q = u & 3;
            cp_async16(smem_u32(sB + r * SA + q * 8),
                       B1 + (size_t)r * K + koff + q * 8);
        }
        CP_COMMIT();
    };

    load_chunk(0, 0);
    load_chunk(1, 32);

    for (int c = 0; c < CC; c++) {
        if (c < CC - 1) CP_WAIT(1); else CP_WAIT(0);
        __syncthreads();
        if (c + 2 < CC) load_chunk((c + 2) % 3, (c + 2) << 5);
        const __half* s  = sm + (c % 3) * STAGE_ELEMS;
        const __half* sB = s + 64 * SA;
        #pragma unroll
        for (int ks = 0; ks < 2; ks++) {
            uint32_t a[2][4], b[8][2];
            const int kc = ks * 16 + tid4 * 2;
            #pragma unroll
            for (int mi = 0; mi < 2; mi++) {
                int r0 = wm * 32 + mi * 16 + gid;
                a[mi][0] = *(const uint32_t*)(s + (size_t)r0 * SA + kc);
                a[mi][1] = *(const uint32_t*)(s + (size_t)(r0 + 8) * SA + kc);
                a[mi][2] = *(const uint32_t*)(s + (size_t)r0 * SA + kc + 8);
                a[mi][3] = *(const uint32_t*)(s + (size_t)(r0 + 8) * SA + kc + 8);
            }
            #pragma unroll
            for (int ni = 0; ni < 8; ni++) {
                int n0 = wn * 64 + ni * 8 + gid;
                b[ni][0] = *(const uint32_t*)(sB + (size_t)n0 * SA + kc);
                b[ni][1] = *(const uint32_t*)(sB + (size_t)n0 * SA + kc + 8);
            }
            #pragma unroll
            for (int mi = 0; mi < 2; mi++)
                #pragma unroll
                for (int ni = 0; ni < 8; ni++)
                    mma16816(acc[mi][ni], a[mi], b[ni]);
        }
    }

    // epilogue -> fp16
    #pragma unroll
    for (int mi = 0; mi < 2; mi++) {
        int r = row0 + wm * 32 + mi * 16 + gid;
        #pragma unroll
        for (int ni = 0; ni < 8; ni++) {
            int cidx = wn * 64 + ni * 8 + tid4 * 2;
            if (r < M)
                *(__half2*)(C + (size_t)r * 256 + cidx) =
                    __floats2half2_rn(acc[mi][ni][0], acc[mi][ni][1]);
            if (r + 8 < M)
                *(__half2*)(C + (size_t)(r + 8) * 256 + cidx) =
                    __floats2half2_rn(acc[mi][ni][2], acc[mi][ni][3]);
        }
    }
}

// ---------------- SpMM: warp-per-row, LDG.128 gathers ----------------
__device__ __forceinline__ void fma8(float* acc, float v, uint4 raw) {
    float2 f0 = __half22float2(*(__half2*)&raw.x);
    float2 f1 = __half22float2(*(__half2*)&raw.y);
    float2 f2 = __half22float2(*(__half2*)&raw.z);
    float2 f3 = __half22float2(*(__half2*)&raw.w);
    acc[0] = fmaf(v, f0.x, acc[0]);
    acc[1] = fmaf(v, f0.y, acc[1]);
    acc[2] = fmaf(v, f1.x, acc[2]);
    acc[3] = fmaf(v, f1.y, acc[3]);
    acc[4] = fmaf(v, f2.x, acc[4]);
    acc[5] = fmaf(v, f2.y, acc[5]);
    acc[6] = fmaf(v, f3.x, acc[6]);
    acc[7] = fmaf(v, f3.y, acc[7]);
}

__device__ __forceinline__ void spmm_row_w(const uint4* __restrict__ sup4,
                                           int row, int lane, float* acc) {
    int s = g_rowptr[row];
    int e = g_rowptr[row + 1];
    float acc1[8];
    #pragma unroll
    for (int q = 0; q < 8; q++) { acc[q] = 0.f; acc1[q] = 0.f; }
    int i = s;
    for (; i + 4 <= e; i += 4) {
        int2 e0 = __ldg(&g_edges[i]);
        int2 e1 = __ldg(&g_edges[i + 1]);
        int2 e2 = __ldg(&g_edges[i + 2]);
        int2 e3 = __ldg(&g_edges[i + 3]);
        uint4 r0 = __ldg(&sup4[(size_t)e0.x * 32 + lane]);
        uint4 r1 = __ldg(&sup4[(size_t)e1.x * 32 + lane]);
        uint4 r2 = __ldg(&sup4[(size_t)e2.x * 32 + lane]);
        uint4 r3 = __ldg(&sup4[(size_t)e3.x * 32 + lane]);
        fma8(acc,  __int_as_float(e0.y), r0);
        fma8(acc1, __int_as_float(e1.y), r1);
        fma8(acc,  __int_as_float(e2.y), r2);
        fma8(acc1, __int_as_float(e3.y), r3);
    }
    for (; i < e; i++) {
        int2 ed = __ldg(&g_edges[i]);
        uint4 r0 = __ldg(&sup4[(size_t)ed.x * 32 + lane]);
        fma8(acc, __int_as_float(ed.y), r0);
    }
    #pragma unroll
    for (int q = 0; q < 8; q++) acc[q] += acc1[q];
}

// writes next layer's fp16 A operand (stride 256)
__global__ void __launch_bounds__(256)
spmm_h16_kernel(const uint4* __restrict__ sup4,
                const float4* __restrict__ bias,
                __half* __restrict__ a_next, int nrows) {
    const int row  = blockIdx.x * 8 + (threadIdx.x >> 5);
    const int lane = threadIdx.x & 31;
    if (row >= nrows) return;
    float acc[8];
    spmm_row_w(sup4, row, lane, acc);
    float4 b0 = __ldg(&bias[lane * 2]);
    float4 b1 = __ldg(&bias[lane * 2 + 1]);
    float v0 = fmaxf(acc[0] + b0.x, 0.f), v1 = fmaxf(acc[1] + b0.y, 0.f);
    float v2 = fmaxf(acc[2] + b0.z, 0.f), v3 = fmaxf(acc[3] + b0.w, 0.f);
    float v4 = fmaxf(acc[4] + b1.x, 0.f), v5 = fmaxf(acc[5] + b1.y, 0.f);
    float v6 = fmaxf(acc[6] + b1.z, 0.f), v7 = fmaxf(acc[7] + b1.w, 0.f);
    __half2 h0 = __floats2half2_rn(v0, v1);
    __half2 h1 = __floats2half2_rn(v2, v3);
    __half2 h2 = __floats2half2_rn(v4, v5);
    __half2 h3 = __floats2half2_rn(v6, v7);
    uint4 o;
    o.x = *(uint32_t*)&h0; o.y = *(uint32_t*)&h1;
    o.z = *(uint32_t*)&h2; o.w = *(uint32_t*)&h3;
    *(uint4*)(a_next + (size_t)row * 256 + lane * 8) = o;
}

// Layer-3 SpMM fused with the output permutation: rows < N_XROWS,
// writes relu(agg + b) directly at out[pos[row]].
__global__ void __launch_bounds__(256)
spmm_out_kernel(const uint4* __restrict__ sup4,
                const float4* __restrict__ bias,
                const int* __restrict__ pos,
                float4* __restrict__ out, int nrows) {
    const int row  = blockIdx.x * 8 + (threadIdx.x >> 5);
    const int lane = threadIdx.x & 31;
    if (row >= nrows) return;
    float acc[8];
    spmm_row_w(sup4, row, lane, acc);
    float4 b0 = __ldg(&bias[lane * 2]);
    float4 b1 = __ldg(&bias[lane * 2 + 1]);
    float4 o0, o1;
    o0.x = fmaxf(acc[0] + b0.x, 0.f); o0.y = fmaxf(acc[1] + b0.y, 0.f);
    o0.z = fmaxf(acc[2] + b0.z, 0.f); o0.w = fmaxf(acc[3] + b0.w, 0.f);
    o1.x = fmaxf(acc[4] + b1.x, 0.f); o1.y = fmaxf(acc[5] + b1.y, 0.f);
    o1.z = fmaxf(acc[6] + b1.z, 0.f); o1.w = fmaxf(acc[7] + b1.w, 0.f);
    size_t base = (size_t)__ldg(&pos[row]) * 64 + lane * 2;
    out[base]     = o0;
    out[base + 1] = o1;
}

// ---------------- output zero ----------------
__global__ void zero_out_kernel(float4* __restrict__ out, int n4) {
    int i = blockIdx.x * 256 + threadIdx.x;
    if (i < n4) out[i] = make_float4(0.f, 0.f, 0.f, 0.f);
}

// ---------------- launch ----------------
extern "C" void kernel_launch(void* const* d_in, const int* in_sizes, int n_in,
                              void* d_out, int out_size) {
    const float* x     = (const float*)d_in[0];
    const float* motif = (const float*)d_in[1];
    const int*   rows  = (const int*)d_in[2];
    const int*   cols  = (const int*)d_in[3];
    const float* vals  = (const float*)d_in[4];
    const int*   pos   = (const int*)d_in[5];
    int wi = 6;
    if (n_in >= 13 && in_sizes[6] == 1) wi = 7;
    const float* w1 = (const float*)d_in[wi + 0];
    const float* b1 = (const float*)d_in[wi + 1];
    const float* w2 = (const float*)d_in[wi + 2];
    const float* b2 = (const float*)d_in[wi + 3];
    const float* w3 = (const float*)d_in[wi + 4];
    const float* b3 = (const float*)d_in[wi + 5];

    __half *support, *a, *bt1, *bt2, *bt3;
    cudaGetSymbolAddress((void**)&support, g_support);
    cudaGetSymbolAddress((void**)&a, g_a);
    cudaGetSymbolAddress((void**)&bt1, g_b1);
    cudaGetSymbolAddress((void**)&bt2, g_b2);
    cudaGetSymbolAddress((void**)&bt3, g_b3);

    cudaFuncSetAttribute(hmma_gemm_kernel,
                         cudaFuncAttributeMaxDynamicSharedMemorySize, GEMM_SMEM);

    // R9 schedule (best measured) with the parallel scan substituted.
    // ONE side stream; created per call, intentionally not destroyed
    // mid-capture.
    cudaStream_t s2;
    cudaStreamCreateWithFlags(&s2, cudaStreamNonBlocking);
    cudaEvent_t evFork, evJoin;
    cudaEventCreateWithFlags(&evFork, cudaEventDisableTiming);
    cudaEventCreateWithFlags(&evJoin, cudaEventDisableTiming);

    cudaEventRecord(evFork, 0);
    cudaStreamWaitEvent(s2, evFork, 0);

    const int gemm_grid = M_PAD / 64;    // 938, full-N CTAs
    const int spmm_grid = (N_TOT + 7) / 8;
    const int spmo_grid = (N_XROWS + 7) / 8;
    int n4 = out_size / 4;

    // --- side chain (s2): CSR build (parallel scan) + zero output ---
    zero_cnt_kernel<<<(N_TOT + 255) / 256, 256, 0, s2>>>();
    hist_kernel<<<E_TOT / 256, 256, 0, s2>>>(rows);
    scan_local_kernel<<<NB_SCAN, 1024, 0, s2>>>();
    scan_sums_kernel<<<1, 64, 0, s2>>>();
    scan_add_kernel<<<NB_SCAN, 1024, 0, s2>>>();
    scatter_edges_kernel<<<E_TOT / 256, 256, 0, s2>>>(rows, cols, vals);
    zero_out_kernel<<<(n4 + 255) / 256, 256, 0, s2>>>((float4*)d_out, n4);
    cudaEventRecord(evJoin, s2);

    // --- main chain: weights + A convert + layer-1 GEMM ---
    convertB_kernel<<<512, 256>>>(w1, 512, bt1);
    convertB_kernel<<<256, 256>>>(w2, 256, bt2);
    convertB_kernel<<<256, 256>>>(w3, 256, bt3);
    convertA_kernel<<<(N_TOT * 128) / 256, 256>>>(x, motif, a);
    hmma_gemm_kernel<<<gemm_grid, 256, GEMM_SMEM>>>(a, bt1, support, 512, N_TOT);

    // join: SpMM needs CSR; final spmm_out also needs zeroed output
    cudaStreamWaitEvent(0, evJoin, 0);
    spmm_h16_kernel<<<spmm_grid, 256>>>((const uint4*)support,
                                        (const float4*)b1, a, N_TOT);

    // --- layer 2 (K=256) ---
    hmma_gemm_kernel<<<gemm_grid, 256, GEMM_SMEM>>>(a, bt2, support, 256, N_TOT);
    spmm_h16_kernel<<<spmm_grid, 256>>>((const uint4*)support,
                                        (const float4*)b2, a, N_TOT);

    // --- layer 3 (K=256): SpMM fused with output scatter ---
    hmma_gemm_kernel<<<gemm_grid, 256, GEMM_SMEM>>>(a, bt3, support, 256, N_TOT);
    spmo_grid;
    spmm_out_kernel<<<spmo_grid, 256>>>((const uint4*)support,
                                        (const float4*)b3, pos,
                                        (float4*)d_out, N_XROWS);
}

// round 15
// speedup vs baseline: 1.2107x; 1.0456x over previous
#include <cuda_runtime.h>
#include <cuda_fp16.h>
#include <cstdint>

#define N_XROWS   50000
#define N_MOTIF   10000
#define N_TOT     60000
#define E_TOT     1920000
#define NHID      256
#define PAD_N     65536
#define M_PAD     60032          // 938 * 64
#define NB_SCAN   ((N_TOT + 1023) / 1024)   // 59

// ---------------- device scratch (no allocs allowed) ----------------
__device__ int   g_cnt[N_TOT];
__device__ int   g_cur[N_TOT];
__device__ int   g_rowptr[N_TOT + 1];
__device__ int   g_bsum[64];
__device__ int2  g_edges[E_TOT];
__device__ __half g_support[(size_t)N_TOT * NHID];     // fp16 support
__device__ __half g_a[(size_t)M_PAD * 256];            // inter-layer A, fp16
__device__ __half g_b1[256 * 512];                     // W1^T fp16, K-major
__device__ __half g_b2[256 * 256];                     // W2^T fp16
__device__ __half g_b3[256 * 256];                     // W3^T fp16

// ================= helpers =================
__device__ __forceinline__ uint32_t smem_u32(const void* p) {
    uint32_t a;
    asm("{ .reg .u64 t; cvta.to.shared.u64 t, %1; cvt.u32.u64 %0, t; }"
        : "=r"(a) : "l"(p));
    return a;
}
__device__ __forceinline__ void cp_async16(uint32_t dst, const void* src) {
    asm volatile("cp.async.cg.shared.global [%0], [%1], 16;"
                 :: "r"(dst), "l"(__cvta_generic_to_global(src)) : "memory");
}
#define CP_COMMIT() asm volatile("cp.async.commit_group;" ::: "memory")
#define CP_WAIT(n)  asm volatile("cp.async.wait_group %0;" :: "n"(n) : "memory")

__device__ __forceinline__ void mma16816(float* d, const uint32_t* a,
                                         const uint32_t* b) {
    asm volatile(
        "mma.sync.aligned.m16n8k16.row.col.f32.f16.f16.f32 "
        "{%0,%1,%2,%3}, {%4,%5,%6,%7}, {%8,%9}, {%0,%1,%2,%3};"
        : "+f"(d[0]), "+f"(d[1]), "+f"(d[2]), "+f"(d[3])
        : "r"(a[0]), "r"(a[1]), "r"(a[2]), "r"(a[3]), "r"(b[0]), "r"(b[1]));
}

__device__ __forceinline__ uint64_t pack4h(__half a, __half b, __half c, __half d) {
    __half2 p0 = __halves2half2(a, b);
    __half2 p1 = __halves2half2(c, d);
    uint32_t u0 = *(uint32_t*)&p0;
    uint32_t u1 = *(uint32_t*)&p1;
    return (uint64_t)u0 | ((uint64_t)u1 << 32);
}

__device__ __forceinline__ uint32_t ldcvt_h2(const float* p) {
    float2 v = *(const float2*)p;
    __half2 h = __floats2half2_rn(v.x, v.y);
    return *(uint32_t*)&h;
}

// ---------------- CSR build (packed, parallel scan) ----------------
__global__ void zero_cnt_kernel() {
    int i = blockIdx.x * 256 + threadIdx.x;
    if (i < N_TOT) { g_cnt[i] = 0; g_cur[i] = 0; }
}
__global__ void hist_kernel(const int* __restrict__ rows) {
    int i = blockIdx.x * 256 + threadIdx.x;
    if (i < E_TOT) atomicAdd(&g_cnt[rows[i]], 1);
}

__global__ void scan_local_kernel() {
    __shared__ int wsum[32];
    const int tid = threadIdx.x;
    const int lane = tid & 31, wid = tid >> 5;
    int i = blockIdx.x * 1024 + tid;
    int x = (i < N_TOT) ? g_cnt[i] : 0;
    int v = x;
    #pragma unroll
    for (int off = 1; off < 32; off <<= 1) {
        int u = __shfl_up_sync(0xffffffffu, v, off);
        if (lane >= off) v += u;
    }
    if (lane == 31) wsum[wid] = v;
    __syncthreads();
    if (wid == 0) {
        int w = wsum[lane];
        #pragma unroll
        for (int off = 1; off < 32; off <<= 1) {
            int u = __shfl_up_sync(0xffffffffu, w, off);
            if (lane >= off) w += u;
        }
        wsum[lane] = w;
    }
    __syncthreads();
    int warp_prefix = (wid == 0) ? 0 : wsum[wid - 1];
    int excl = warp_prefix + v - x;
    if (i < N_TOT) g_rowptr[i] = excl;
    if (tid == 1023) g_bsum[blockIdx.x] = excl + x;
}

__global__ void scan_sums_kernel() {
    __shared__ int w0sum;
    const int tid = threadIdx.x;           // 64 threads, 2 warps
    const int lane = tid & 31, wid = tid >> 5;
    int x = (tid < NB_SCAN) ? g_bsum[tid] : 0;
    int v = x;
    #pragma unroll
    for (int off = 1; off < 32; off <<= 1) {
        int u = __shfl_up_sync(0xffffffffu, v, off);
        if (lane >= off) v += u;
    }
    if (wid == 0 && lane == 31) w0sum = v;
    __syncthreads();
    int excl = v - x + ((wid == 1) ? w0sum : 0);
    if (tid < NB_SCAN) g_bsum[tid] = excl;
    if (tid == 0) g_rowptr[N_TOT] = E_TOT;
}

__global__ void scan_add_kernel() {
    int i = blockIdx.x * 1024 + threadIdx.x;
    if (i < N_TOT) g_rowptr[i] += g_bsum[blockIdx.x];
}

__global__ void scatter_edges_kernel(const int* __restrict__ rows,
                                     const int* __restrict__ cols,
                                     const float* __restrict__ vals) {
    int i = blockIdx.x * 256 + threadIdx.x;
    if (i < E_TOT) {
        int r = rows[i];
        int pos = g_rowptr[r] + atomicAdd(&g_cur[r], 1);
        g_edges[pos] = make_int2(cols[i], __float_as_int(vals[i]));
    }
}

// ---------------- fp16 weight conversion (all 3 in one launch) --------
// w1: 512x256, w2/w3: 256x256 -> K-major transposed fp16
__global__ void convertB3_kernel(const float* __restrict__ w1,
                                 const float* __restrict__ w2,
                                 const float* __restrict__ w3,
                                 __half* __restrict__ o1,
                                 __half* __restrict__ o2,
                                 __half* __restrict__ o3) {
    int idx = blockIdx.x * 256 + threadIdx.x;   // 262144 total
    if (idx < 512 * 256) {
        int k = idx >> 8, n = idx & 255;
        o1[(size_t)n * 512 + k] = __float2half_rn(w1[idx]);
    } else if (idx < (512 + 256) * 256) {
        int j = idx - 512 * 256;
        int k = j >> 8, n = j & 255;
        o2[(size_t)n * 256 + k] = __float2half_rn(w2[j]);
    } else if (idx < (512 + 512) * 256) {
        int j = idx - (512 + 256) * 256;
        int k = j >> 8, n = j & 255;
        o3[(size_t)n * 256 + k] = __float2half_rn(w3[j]);
    }
}

// ---------------- HMMA GEMM (fp16 A): C = A16 @ B16^T ----
// CTA tile 64x256 (full N), BK=32, 8 warps as 2(M) x 4(N), warp tile 32x64.
#define SA 40                               // padded SMEM row stride (halfs)
#define STAGE_ELEMS ((64 + 256) * SA)       // 12800 halfs
#define GEMM_SMEM   (3 * STAGE_ELEMS * 2)   // 76800 bytes

__global__ void __launch_bounds__(256, 2)
hmma_gemm_kernel(const __half* __restrict__ A,
                 const __half* __restrict__ B1,
                 __half* __restrict__ C, int K, int M) {
    extern __shared__ __half sm[];
    const int t    = threadIdx.x;
    const int lane = t & 31, wid = t >> 5;
    const int wm   = wid & 1, wn = wid >> 1;
    const int gid  = lane >> 2, tid4 = lane & 3;
    const int row0 = blockIdx.x * 64;
    const int CC = K >> 5;

    float acc[2][8][4];
    #pragma unroll
    for (int mi = 0; mi < 2; mi++)
        #pragma unroll
        for (int ni = 0; ni < 8; ni++)
            #pragma unroll
            for (int q = 0; q < 4; q++) acc[mi][ni][q] = 0.f;

    auto load_chunk = [&](int stage, int koff) {
        __half* s  = sm + stage * STAGE_ELEMS;
        __half* sB = s + 64 * SA;
        {
            int r = t >> 2, q = t & 3;
            cp_async16(smem_u32(s + r * SA + q * 8),
                       A + (size_t)(row0 + r) * K + koff + q * 8);
        }
        #pragma unroll
        for (int j = 0; j < 4; j++) {
            int u = j * 256 + t;
            int r = u >> 2, q = u & 3;
            cp_async16(smem_u32(sB + r * SA + q * 8),
                       B1 + (size_t)r * K + koff + q * 8);
        }
        CP_COMMIT();
    };

    load_chunk(0, 0);
    load_chunk(1, 32);

    for (int c = 0; c < CC; c++) {
        if (c < CC - 1) CP_WAIT(1); else CP_WAIT(0);
        __syncthreads();
        if (c + 2 < CC) load_chunk((c + 2) % 3, (c + 2) << 5);
        const __half* s  = sm + (c % 3) * STAGE_ELEMS;
        const __half* sB = s + 64 * SA;
        #pragma unroll
        for (int ks = 0; ks < 2; ks++) {
            uint32_t a[2][4], b[8][2];
            const int kc = ks * 16 + tid4 * 2;
            #pragma unroll
            for (int mi = 0; mi < 2; mi++) {
                int r0 = wm * 32 + mi * 16 + gid;
                a[mi][0] = *(const uint32_t*)(s + (size_t)r0 * SA + kc);
                a[mi][1] = *(const uint32_t*)(s + (size_t)(r0 + 8) * SA + kc);
                a[mi][2] = *(const uint32_t*)(s + (size_t)r0 * SA + kc + 8);
                a[mi][3] = *(const uint32_t*)(s + (size_t)(r0 + 8) * SA + kc + 8);
            }
            #pragma unroll
            for (int ni = 0; ni < 8; ni++) {
                int n0 = wn * 64 + ni * 8 + gid;
                b[ni][0] = *(const uint32_t*)(sB + (size_t)n0 * SA + kc);
                b[ni][1] = *(const uint32_t*)(sB + (size_t)n0 * SA + kc + 8);
            }
            #pragma unroll
            for (int mi = 0; mi < 2; mi++)
                #pragma unroll
                for (int ni = 0; ni < 8; ni++)
                    mma16816(acc[mi][ni], a[mi], b[ni]);
        }
    }

    #pragma unroll
    for (int mi = 0; mi < 2; mi++) {
        int r = row0 + wm * 32 + mi * 16 + gid;
        #pragma unroll
        for (int ni = 0; ni < 8; ni++) {
            int cidx = wn * 64 + ni * 8 + tid4 * 2;
            if (r < M)
                *(__half2*)(C + (size_t)r * 256 + cidx) =
                    __floats2half2_rn(acc[mi][ni][0], acc[mi][ni][1]);
            if (r + 8 < M)
                *(__half2*)(C + (size_t)(r + 8) * 256 + cidx) =
                    __floats2half2_rn(acc[mi][ni][2], acc[mi][ni][3]);
        }
    }
}

// ---------------- HMMA GEMM (fp32 A, fused convert): layer 1 ----
// A rows come directly from x (rows < N_XROWS) / motif; K = 512 fixed.
// A staged as fp32 in smem; fragments converted at load (cvt to half2).
#define SAF 36                              // fp32 A smem stride (floats)
#define ASTAGE_B (64 * SAF * 4)             // 9216 bytes
#define BSTAGE_B (256 * SA * 2)             // 20480 bytes
#define STAGE_B  (ASTAGE_B + BSTAGE_B)      // 29696 bytes
#define GEMMF_SMEM (3 * STAGE_B)            // 89088 bytes
#define KF 512

__global__ void __launch_bounds__(256, 2)
hmma_gemm_f32a_kernel(const float* __restrict__ X,
                      const float* __restrict__ MOTIF,
                      const __half* __restrict__ B1,
                      __half* __restrict__ C) {
    extern __shared__ char smc[];
    const int t    = threadIdx.x;
    const int lane = t & 31, wid = t >> 5;
    const int wm   = wid & 1, wn = wid >> 1;
    const int gid  = lane >> 2, tid4 = lane & 3;
    const int row0 = blockIdx.x * 64;
    const int CC = KF >> 5;                 // 16 chunks

    float acc[2][8][4];
    #pragma unroll
    for (int mi = 0; mi < 2; mi++)
        #pragma unroll
        for (int ni = 0; ni < 8; ni++)
            #pragma unroll
            for (int q = 0; q < 4; q++) acc[mi][ni][q] = 0.f;

    auto load_chunk = [&](int stage, int koff) {
        float*  sAf = (float*)(smc + stage * STAGE_B);
        __half* sB  = (__half*)(smc + stage * STAGE_B + ASTAGE_B);
        #pragma unroll
        for (int j = 0; j < 2; j++) {        // A: 64 rows x 32 floats
            int u = j * 256 + t;
            int r = u >> 3, q = u & 7;       // q: 4-float group
            int gm = row0 + r;
            if (gm >= N_TOT) gm = N_TOT - 1; // clamp padding rows (discarded)
            const float* src = (gm < N_XROWS)
                ? X + (size_t)gm * KF + koff + q * 4
                : MOTIF + (size_t)(gm - N_XROWS) * KF + koff + q * 4;
            cp_async16(smem_u32(sAf + r * SAF + q * 4), src);
        }
        #pragma unroll
        for (int j = 0; j < 4; j++) {        // B: 256 rows x 32 halfs
            int u = j * 256 + t;
            int r = u >> 2, q = u & 3;
            cp_async16(smem_u32(sB + r * SA + q * 8),
                       B1 + (size_t)r * KF + koff + q * 8);
        }
        CP_COMMIT();
    };

    load_chunk(0, 0);
    load_chunk(1, 32);

    for (int c = 0; c < CC; c++) {
        if (c < CC - 1) CP_WAIT(1); else CP_WAIT(0);
        __syncthreads();
        if (c + 2 < CC) load_chunk((c + 2) % 3, (c + 2) << 5);
        const float*  sAf = (const float*)(smc + (c % 3) * STAGE_B);
        const __half* sB  = (const __half*)(smc + (c % 3) * STAGE_B + ASTAGE_B);
        #pragma unroll
        for (int ks = 0; ks < 2; ks++) {
            uint32_t a[2][4], b[8][2];
            const int kc = ks * 16 + tid4 * 2;
            #pragma unroll
            for (int mi = 0; mi < 2; mi++) {
                int r0 = wm * 32 + mi * 16 + gid;
                a[mi][0] = ldcvt_h2(sAf + (size_t)r0 * SAF + kc);
                a[mi][1] = ldcvt_h2(sAf + (size_t)(r0 + 8) * SAF + kc);
                a[mi][2] = ldcvt_h2(sAf + (size_t)r0 * SAF + kc + 8);
                a[mi][3] = ldcvt_h2(sAf + (size_t)(r0 + 8) * SAF + kc + 8);
            }
            #pragma unroll
            for (int ni = 0; ni < 8; ni++) {
                int n0 = wn * 64 + ni * 8 + gid;
                b[ni][0] = *(const uint32_t*)(sB + (size_t)n0 * SA + kc);
                b[ni][1] = *(const uint32_t*)(sB + (size_t)n0 * SA + kc + 8);
            }
            #pragma unroll
            for (int mi = 0; mi < 2; mi++)
                #pragma unroll
                for (int ni = 0; ni < 8; ni++)
                    mma16816(acc[mi][ni], a[mi], b[ni]);
        }
    }

    #pragma unroll
    for (int mi = 0; mi < 2; mi++) {
        int r = row0 + wm * 32 + mi * 16 + gid;
        #pragma unroll
        for (int ni = 0; ni < 8; ni++) {
            int cidx = wn * 64 + ni * 8 + tid4 * 2;
            if (r < N_TOT)
                *(__half2*)(C + (size_t)r * 256 + cidx) =
                    __floats2half2_rn(acc[mi][ni][0], acc[mi][ni][1]);
            if (r + 8 < N_TOT)
                *(__half2*)(C + (size_t)(r + 8) * 256 + cidx) =
                    __floats2half2_rn(acc[mi][ni][2], acc[mi][ni][3]);
        }
    }
}

// ---------------- SpMM: warp-per-row, LDG.128 gathers ----------------
__device__ __forceinline__ void fma8(float* acc, float v, uint4 raw) {
    float2 f0 = __half22float2(*(__half2*)&raw.x);
    float2 f1 = __half22float2(*(__half2*)&raw.y);
    float2 f2 = __half22float2(*(__half2*)&raw.z);
    float2 f3 = __half22float2(*(__half2*)&raw.w);
    acc[0] = fmaf(v, f0.x, acc[0]);
    acc[1] = fmaf(v, f0.y, acc[1]);
    acc[2] = fmaf(v, f1.x, acc[2]);
    acc[3] = fmaf(v, f1.y, acc[3]);
    acc[4] = fmaf(v, f2.x, acc[4]);
    acc[5] = fmaf(v, f2.y, acc[5]);
    acc[6] = fmaf(v, f3.x, acc[6]);
    acc[7] = fmaf(v, f3.y, acc[7]);
}

__device__ __forceinline__ void spmm_row_w(const uint4* __restrict__ sup4,
                                           int row, int lane, float* acc) {
    int s = g_rowptr[row];
    int e = g_rowptr[row + 1];
    float acc1[8];
    #pragma unroll
    for (int q = 0; q < 8; q++) { acc[q] = 0.f; acc1[q] = 0.f; }
    int i = s;
    for (; i + 4 <= e; i += 4) {
        int2 e0 = __ldg(&g_edges[i]);
        int2 e1 = __ldg(&g_edges[i + 1]);
        int2 e2 = __ldg(&g_edges[i + 2]);
        int2 e3 = __ldg(&g_edges[i + 3]);
        uint4 r0 = __ldg(&sup4[(size_t)e0.x * 32 + lane]);
        uint4 r1 = __ldg(&sup4[(size_t)e1.x * 32 + lane]);
        uint4 r2 = __ldg(&sup4[(size_t)e2.x * 32 + lane]);
        uint4 r3 = __ldg(&sup4[(size_t)e3.x * 32 + lane]);
        fma8(acc,  __int_as_float(e0.y), r0);
        fma8(acc1, __int_as_float(e1.y), r1);
        fma8(acc,  __int_as_float(e2.y), r2);
        fma8(acc1, __int_as_float(e3.y), r3);
    }
    for (; i < e; i++) {
        int2 ed = __ldg(&g_edges[i]);
        uint4 r0 = __ldg(&sup4[(size_t)ed.x * 32 + lane]);
        fma8(acc, __int_as_float(ed.y), r0);
    }
    #pragma unroll
    for (int q = 0; q < 8; q++) acc[q] += acc1[q];
}

// writes next layer's fp16 A operand (stride 256)
__global__ void __launch_bounds__(256)
spmm_h16_kernel(const uint4* __restrict__ sup4,
                const float4* __restrict__ bias,
                __half* __restrict__ a_next, int nrows) {
    const int row  = blockIdx.x * 8 + (threadIdx.x >> 5);
    const int lane = threadIdx.x & 31;
    if (row >= nrows) return;
    float acc[8];
    spmm_row_w(sup4, row, lane, acc);
    float4 b0 = __ldg(&bias[lane * 2]);
    float4 b1 = __ldg(&bias[lane * 2 + 1]);
    float v0 = fmaxf(acc[0] + b0.x, 0.f), v1 = fmaxf(acc[1] + b0.y, 0.f);
    float v2 = fmaxf(acc[2] + b0.z, 0.f), v3 = fmaxf(acc[3] + b0.w, 0.f);
    float v4 = fmaxf(acc[4] + b1.x, 0.f), v5 = fmaxf(acc[5] + b1.y, 0.f);
    float v6 = fmaxf(acc[6] + b1.z, 0.f), v7 = fmaxf(acc[7] + b1.w, 0.f);
    __half2 h0 = __floats2half2_rn(v0, v1);
    __half2 h1 = __floats2half2_rn(v2, v3);
    __half2 h2 = __floats2half2_rn(v4, v5);
    __half2 h3 = __floats2half2_rn(v6, v7);
    uint4 o;
    o.x = *(uint32_t*)&h0; o.y = *(uint32_t*)&h1;
    o.z = *(uint32_t*)&h2; o.w = *(uint32_t*)&h3;
    *(uint4*)(a_next + (size_t)row * 256 + lane * 8) = o;
}

// Layer-3 SpMM fused with the output permutation.
__global__ void __launch_bounds__(256)
spmm_out_kernel(const uint4* __restrict__ sup4,
                const float4* __restrict__ bias,
                const int* __restrict__ pos,
                float4* __restrict__ out, int nrows) {
    const int row  = blockIdx.x * 8 + (threadIdx.x >> 5);
    const int lane = threadIdx.x & 31;
    if (row >= nrows) return;
    float acc[8];
    spmm_row_w(sup4, row, lane, acc);
    float4 b0 = __ldg(&bias[lane * 2]);
    float4 b1 = __ldg(&bias[lane * 2 + 1]);
    float4 o0, o1;
    o0.x = fmaxf(acc[0] + b0.x, 0.f); o0.y = fmaxf(acc[1] + b0.y, 0.f);
    o0.z = fmaxf(acc[2] + b0.z, 0.f); o0.w = fmaxf(acc[3] + b0.w, 0.f);
    o1.x = fmaxf(acc[4] + b1.x, 0.f); o1.y = fmaxf(acc[5] + b1.y, 0.f);
    o1.z = fmaxf(acc[6] + b1.z, 0.f); o1.w = fmaxf(acc[7] + b1.w, 0.f);
    size_t base = (size_t)__ldg(&pos[row]) * 64 + lane * 2;
    out[base]     = o0;
    out[base + 1] = o1;
}

// ---------------- output zero ----------------
__global__ void zero_out_kernel(float4* __restrict__ out, int n4) {
    int i = blockIdx.x * 256 + threadIdx.x;
    if (i < n4) out[i] = make_float4(0.f, 0.f, 0.f, 0.f);
}

// ---------------- launch ----------------
extern "C" void kernel_launch(void* const* d_in, const int* in_sizes, int n_in,
                              void* d_out, int out_size) {
    const float* x     = (const float*)d_in[0];
    const float* motif = (const float*)d_in[1];
    const int*   rows  = (const int*)d_in[2];
    const int*   cols  = (const int*)d_in[3];
    const float* vals  = (const float*)d_in[4];
    const int*   pos   = (const int*)d_in[5];
    int wi = 6;
    if (n_in >= 13 && in_sizes[6] == 1) wi = 7;
    const float* w1 = (const float*)d_in[wi + 0];
    const float* b1 = (const float*)d_in[wi + 1];
    const float* w2 = (const float*)d_in[wi + 2];
    const float* b2 = (const float*)d_in[wi + 3];
    const float* w3 = (const float*)d_in[wi + 4];
    const float* b3 = (const float*)d_in[wi + 5];

    __half *support, *a, *bt1, *bt2, *bt3;
    cudaGetSymbolAddress((void**)&support, g_support);
    cudaGetSymbolAddress((void**)&a, g_a);
    cudaGetSymbolAddress((void**)&bt1, g_b1);
    cudaGetSymbolAddress((void**)&bt2, g_b2);
    cudaGetSymbolAddress((void**)&bt3, g_b3);

    cudaFuncSetAttribute(hmma_gemm_kernel,
                         cudaFuncAttributeMaxDynamicSharedMemorySize, GEMM_SMEM);
    cudaFuncSetAttribute(hmma_gemm_f32a_kernel,
                         cudaFuncAttributeMaxDynamicSharedMemorySize, GEMMF_SMEM);

    // ONE side stream; created per call, intentionally not destroyed
    // mid-capture (graph-capture safety; two-wide graphs pass teardown).
    cudaStream_t s2;
    cudaStreamCreateWithFlags(&s2, cudaStreamNonBlocking);
    cudaEvent_t evFork, evJoin;
    cudaEventCreateWithFlags(&evFork, cudaEventDisableTiming);
    cudaEventCreateWithFlags(&evJoin, cudaEventDisableTiming);

    cudaEventRecord(evFork, 0);
    cudaStreamWaitEvent(s2, evFork, 0);

    const int gemm_grid = M_PAD / 64;    // 938, full-N CTAs
    const int spmm_grid = (N_TOT + 7) / 8;
    const int spmo_grid = (N_XROWS + 7) / 8;
    int n4 = out_size / 4;

    // --- side chain (s2): CSR build (parallel scan) + zero output ---
    zero_cnt_kernel<<<(N_TOT + 255) / 256, 256, 0, s2>>>();
    hist_kernel<<<E_TOT / 256, 256, 0, s2>>>(rows);
    scan_local_kernel<<<NB_SCAN, 1024, 0, s2>>>();
    scan_sums_kernel<<<1, 64, 0, s2>>>();
    scan_add_kernel<<<NB_SCAN, 1024, 0, s2>>>();
    scatter_edges_kernel<<<E_TOT / 256, 256, 0, s2>>>(rows, cols, vals);
    zero_out_kernel<<<(n4 + 255) / 256, 256, 0, s2>>>((float4*)d_out, n4);
    cudaEventRecord(evJoin, s2);

    // --- main chain: weights (one launch) + fused-convert layer-1 GEMM ---
    convertB3_kernel<<<1024, 256>>>(w1, w2, w3, bt1, bt2, bt3);
    hmma_gemm_f32a_kernel<<<gemm_grid, 256, GEMMF_SMEM>>>(x, motif, bt1,
                                                          support);

    // join: SpMM needs CSR; final spmm_out also needs zeroed output
    cudaStreamWaitEvent(0, evJoin, 0);
    spmm_h16_kernel<<<spmm_grid, 256>>>((const uint4*)support,
                                        (const float4*)b1, a, N_TOT);

    // --- layer 2 (K=256) ---
    hmma_gemm_kernel<<<gemm_grid, 256, GEMM_SMEM>>>(a, bt2, support, 256, N_TOT);
    spmm_h16_kernel<<<spmm_grid, 256>>>((const uint4*)support,
                                        (const float4*)b2, a, N_TOT);

    // --- layer 3 (K=256): SpMM fused with output scatter ---
    hmma_gemm_kernel<<<gemm_grid, 256, GEMM_SMEM>>>(a, bt3, support, 256, N_TOT);
    spmm_out_kernel<<<spmo_grid, 256>>>((const uint4*)support,
                                        (const float4*)b3, pos,
                                        (float4*)d_out, N_XROWS);
}

// round 16
// speedup vs baseline: 1.2366x; 1.0214x over previous
#include <cuda_runtime.h>
#include <cuda_fp16.h>
#include <cstdint>

#define N_XROWS   50000
#define N_MOTIF   10000
#define N_TOT     60000
#define E_TOT     1920000
#define NHID      256
#define PAD_N     65536
#define M_PAD     60032          // 938 * 64
#define NB_SCAN   ((N_TOT + 1023) / 1024)   // 59

// ---------------- device scratch (no allocs allowed) ----------------
__device__ int   g_cnt[N_TOT];
__device__ int   g_cur[N_TOT];
__device__ int   g_rowptr[N_TOT + 1];
__device__ int   g_bsum[64];
__device__ int2  g_edges[E_TOT];
__device__ __half g_support[(size_t)N_TOT * NHID];     // fp16 support
__device__ __half g_a[(size_t)M_PAD * 256];            // inter-layer A, fp16
__device__ __half g_b1[256 * 512];                     // W1^T fp16, K-major
__device__ __half g_b2[256 * 256];                     // W2^T fp16
__device__ __half g_b3[256 * 256];                     // W3^T fp16

// ================= helpers =================
__device__ __forceinline__ uint32_t smem_u32(const void* p) {
    uint32_t a;
    asm("{ .reg .u64 t; cvta.to.shared.u64 t, %1; cvt.u32.u64 %0, t; }"
        : "=r"(a) : "l"(p));
    return a;
}
__device__ __forceinline__ void cp_async16(uint32_t dst, const void* src) {
    asm volatile("cp.async.cg.shared.global [%0], [%1], 16;"
                 :: "r"(dst), "l"(__cvta_generic_to_global(src)) : "memory");
}
#define CP_COMMIT() asm volatile("cp.async.commit_group;" ::: "memory")
#define CP_WAIT(n)  asm volatile("cp.async.wait_group %0;" :: "n"(n) : "memory")

__device__ __forceinline__ void mma16816(float* d, const uint32_t* a,
                                         const uint32_t* b) {
    asm volatile(
        "mma.sync.aligned.m16n8k16.row.col.f32.f16.f16.f32 "
        "{%0,%1,%2,%3}, {%4,%5,%6,%7}, {%8,%9}, {%0,%1,%2,%3};"
        : "+f"(d[0]), "+f"(d[1]), "+f"(d[2]), "+f"(d[3])
        : "r"(a[0]), "r"(a[1]), "r"(a[2]), "r"(a[3]), "r"(b[0]), "r"(b[1]));
}

__device__ __forceinline__ uint32_t ldcvt_h2(const float* p) {
    float2 v = *(const float2*)p;
    __half2 h = __floats2half2_rn(v.x, v.y);
    return *(uint32_t*)&h;
}

// ---------------- CSR build (packed, parallel scan) ----------------
__global__ void zero_cnt_kernel() {
    int i = blockIdx.x * 256 + threadIdx.x;
    if (i < N_TOT) { g_cnt[i] = 0; g_cur[i] = 0; }
}
__global__ void hist_kernel(const int* __restrict__ rows) {
    int i = blockIdx.x * 256 + threadIdx.x;
    if (i < E_TOT) atomicAdd(&g_cnt[rows[i]], 1);
}

__global__ void scan_local_kernel() {
    __shared__ int wsum[32];
    const int tid = threadIdx.x;
    const int lane = tid & 31, wid = tid >> 5;
    int i = blockIdx.x * 1024 + tid;
    int x = (i < N_TOT) ? g_cnt[i] : 0;
    int v = x;
    #pragma unroll
    for (int off = 1; off < 32; off <<= 1) {
        int u = __shfl_up_sync(0xffffffffu, v, off);
        if (lane >= off) v += u;
    }
    if (lane == 31) wsum[wid] = v;
    __syncthreads();
    if (wid == 0) {
        int w = wsum[lane];
        #pragma unroll
        for (int off = 1; off < 32; off <<= 1) {
            int u = __shfl_up_sync(0xffffffffu, w, off);
            if (lane >= off) w += u;
        }
        wsum[lane] = w;
    }
    __syncthreads();
    int warp_prefix = (wid == 0) ? 0 : wsum[wid - 1];
    int excl = warp_prefix + v - x;
    if (i < N_TOT) g_rowptr[i] = excl;
    if (tid == 1023) g_bsum[blockIdx.x] = excl + x;
}

__global__ void scan_sums_kernel() {
    __shared__ int w0sum;
    const int tid = threadIdx.x;           // 64 threads, 2 warps
    const int lane = tid & 31, wid = tid >> 5;
    int x = (tid < NB_SCAN) ? g_bsum[tid] : 0;
    int v = x;
    #pragma unroll
    for (int off = 1; off < 32; off <<= 1) {
        int u = __shfl_up_sync(0xffffffffu, v, off);
        if (lane >= off) v += u;
    }
    if (wid == 0 && lane == 31) w0sum = v;
    __syncthreads();
    int excl = v - x + ((wid == 1) ? w0sum : 0);
    if (tid < NB_SCAN) g_bsum[tid] = excl;
    if (tid == 0) g_rowptr[N_TOT] = E_TOT;
}

__global__ void scan_add_kernel() {
    int i = blockIdx.x * 1024 + threadIdx.x;
    if (i < N_TOT) g_rowptr[i] += g_bsum[blockIdx.x];
}

__global__ void scatter_edges_kernel(const int* __restrict__ rows,
                                     const int* __restrict__ cols,
                                     const float* __restrict__ vals) {
    int i = blockIdx.x * 256 + threadIdx.x;
    if (i < E_TOT) {
        int r = rows[i];
        int pos = g_rowptr[r] + atomicAdd(&g_cur[r], 1);
        g_edges[pos] = make_int2(cols[i], __float_as_int(vals[i]));
    }
}

// ---------------- fp16 weight conversion (all 3 in one launch) --------
__global__ void convertB3_kernel(const float* __restrict__ w1,
                                 const float* __restrict__ w2,
                                 const float* __restrict__ w3,
                                 __half* __restrict__ o1,
                                 __half* __restrict__ o2,
                                 __half* __restrict__ o3) {
    int idx = blockIdx.x * 256 + threadIdx.x;   // 262144 total
    if (idx < 512 * 256) {
        int k = idx >> 8, n = idx & 255;
        o1[(size_t)n * 512 + k] = __float2half_rn(w1[idx]);
    } else if (idx < (512 + 256) * 256) {
        int j = idx - 512 * 256;
        int k = j >> 8, n = j & 255;
        o2[(size_t)n * 256 + k] = __float2half_rn(w2[j]);
    } else if (idx < (512 + 512) * 256) {
        int j = idx - (512 + 256) * 256;
        int k = j >> 8, n = j & 255;
        o3[(size_t)n * 256 + k] = __float2half_rn(w3[j]);
    }
}

// ---------------- HMMA GEMM (fp16 A): C = A16 @ B16^T ----
#define SA 40                               // padded SMEM row stride (halfs)
#define STAGE_ELEMS ((64 + 256) * SA)       // 12800 halfs
#define GEMM_SMEM   (3 * STAGE_ELEMS * 2)   // 76800 bytes

__global__ void __launch_bounds__(256, 2)
hmma_gemm_kernel(const __half* __restrict__ A,
                 const __half* __restrict__ B1,
                 __half* __restrict__ C, int K, int M) {
    extern __shared__ __half sm[];
    const int t    = threadIdx.x;
    const int lane = t & 31, wid = t >> 5;
    const int wm   = wid & 1, wn = wid >> 1;
    const int gid  = lane >> 2, tid4 = lane & 3;
    const int row0 = blockIdx.x * 64;
    const int CC = K >> 5;

    float acc[2][8][4];
    #pragma unroll
    for (int mi = 0; mi < 2; mi++)
        #pragma unroll
        for (int ni = 0; ni < 8; ni++)
            #pragma unroll
            for (int q = 0; q < 4; q++) acc[mi][ni][q] = 0.f;

    auto load_chunk = [&](int stage, int koff) {
        __half* s  = sm + stage * STAGE_ELEMS;
        __half* sB = s + 64 * SA;
        {
            int r = t >> 2, q = t & 3;
            cp_async16(smem_u32(s + r * SA + q * 8),
                       A + (size_t)(row0 + r) * K + koff + q * 8);
        }
        #pragma unroll
        for (int j = 0; j < 4; j++) {
            int u = j * 256 + t;
            int r = u >> 2, q = u & 3;
            cp_async16(smem_u32(sB + r * SA + q * 8),
                       B1 + (size_t)r * K + koff + q * 8);
        }
        CP_COMMIT();
    };

    load_chunk(0, 0);
    load_chunk(1, 32);

    for (int c = 0; c < CC; c++) {
        if (c < CC - 1) CP_WAIT(1); else CP_WAIT(0);
        __syncthreads();
        if (c + 2 < CC) load_chunk((c + 2) % 3, (c + 2) << 5);
        const __half* s  = sm + (c % 3) * STAGE_ELEMS;
        const __half* sB = s + 64 * SA;
        #pragma unroll
        for (int ks = 0; ks < 2; ks++) {
            uint32_t a[2][4], b[8][2];
            const int kc = ks * 16 + tid4 * 2;
            #pragma unroll
            for (int mi = 0; mi < 2; mi++) {
                int r0 = wm * 32 + mi * 16 + gid;
                a[mi][0] = *(const uint32_t*)(s + (size_t)r0 * SA + kc);
                a[mi][1] = *(const uint32_t*)(s + (size_t)(r0 + 8) * SA + kc);
                a[mi][2] = *(const uint32_t*)(s + (size_t)r0 * SA + kc + 8);
                a[mi][3] = *(const uint32_t*)(s + (size_t)(r0 + 8) * SA + kc + 8);
            }
            #pragma unroll
            for (int ni = 0; ni < 8; ni++) {
                int n0 = wn * 64 + ni * 8 + gid;
                b[ni][0] = *(const uint32_t*)(sB + (size_t)n0 * SA + kc);
                b[ni][1] = *(const uint32_t*)(sB + (size_t)n0 * SA + kc + 8);
            }
            #pragma unroll
            for (int mi = 0; mi < 2; mi++)
                #pragma unroll
                for (int ni = 0; ni < 8; ni++)
                    mma16816(acc[mi][ni], a[mi], b[ni]);
        }
    }

    #pragma unroll
    for (int mi = 0; mi < 2; mi++) {
        int r = row0 + wm * 32 + mi * 16 + gid;
        #pragma unroll
        for (int ni = 0; ni < 8; ni++) {
            int cidx = wn * 64 + ni * 8 + tid4 * 2;
            if (r < M)
                *(__half2*)(C + (size_t)r * 256 + cidx) =
                    __floats2half2_rn(acc[mi][ni][0], acc[mi][ni][1]);
            if (r + 8 < M)
                *(__half2*)(C + (size_t)(r + 8) * 256 + cidx) =
                    __floats2half2_rn(acc[mi][ni][2], acc[mi][ni][3]);
        }
    }
}

// ---------------- HMMA GEMM (fp32 A, fused convert): layer 1 ----
#define SAF 36                              // fp32 A smem stride (floats)
#define ASTAGE_B (64 * SAF * 4)             // 9216 bytes
#define BSTAGE_B (256 * SA * 2)             // 20480 bytes
#define STAGE_B  (ASTAGE_B + BSTAGE_B)      // 29696 bytes
#define GEMMF_SMEM (3 * STAGE_B)            // 89088 bytes
#define KF 512

__global__ void __launch_bounds__(256, 2)
hmma_gemm_f32a_kernel(const float* __restrict__ X,
                      const float* __restrict__ MOTIF,
                      const __half* __restrict__ B1,
                      __half* __restrict__ C) {
    extern __shared__ char smc[];
    const int t    = threadIdx.x;
    const int lane = t & 31, wid = t >> 5;
    const int wm   = wid & 1, wn = wid >> 1;
    const int gid  = lane >> 2, tid4 = lane & 3;
    const int row0 = blockIdx.x * 64;
    const int CC = KF >> 5;                 // 16 chunks

    float acc[2][8][4];
    #pragma unroll
    for (int mi = 0; mi < 2; mi++)
        #pragma unroll
        for (int ni = 0; ni < 8; ni++)
            #pragma unroll
            for (int q = 0; q < 4; q++) acc[mi][ni][q] = 0.f;

    auto load_chunk = [&](int stage, int koff) {
        float*  sAf = (float*)(smc + stage * STAGE_B);
        __half* sB  = (__half*)(smc + stage * STAGE_B + ASTAGE_B);
        #pragma unroll
        for (int j = 0; j < 2; j++) {        // A: 64 rows x 32 floats
            int u = j * 256 + t;
            int r = u >> 3, q = u & 7;
            int gm = row0 + r;
            if (gm >= N_TOT) gm = N_TOT - 1; // clamp padding rows (discarded)
            const float* src = (gm < N_XROWS)
                ? X + (size_t)gm * KF + koff + q * 4
                : MOTIF + (size_t)(gm - N_XROWS) * KF + koff + q * 4;
            cp_async16(smem_u32(sAf + r * SAF + q * 4), src);
        }
        #pragma unroll
        for (int j = 0; j < 4; j++) {        // B: 256 rows x 32 halfs
            int u = j * 256 + t;
            int r = u >> 2, q = u & 3;
            cp_async16(smem_u32(sB + r * SA + q * 8),
                       B1 + (size_t)r * KF + koff + q * 8);
        }
        CP_COMMIT();
    };

    load_chunk(0, 0);
    load_chunk(1, 32);

    for (int c = 0; c < CC; c++) {
        if (c < CC - 1) CP_WAIT(1); else CP_WAIT(0);
        __syncthreads();
        if (c + 2 < CC) load_chunk((c + 2) % 3, (c + 2) << 5);
        const float*  sAf = (const float*)(smc + (c % 3) * STAGE_B);
        const __half* sB  = (const __half*)(smc + (c % 3) * STAGE_B + ASTAGE_B);
        #pragma unroll
        for (int ks = 0; ks < 2; ks++) {
            uint32_t a[2][4], b[8][2];
            const int kc = ks * 16 + tid4 * 2;
            #pragma unroll
            for (int mi = 0; mi < 2; mi++) {
                int r0 = wm * 32 + mi * 16 + gid;
                a[mi][0] = ldcvt_h2(sAf + (size_t)r0 * SAF + kc);
                a[mi][1] = ldcvt_h2(sAf + (size_t)(r0 + 8) * SAF + kc);
                a[mi][2] = ldcvt_h2(sAf + (size_t)r0 * SAF + kc + 8);
                a[mi][3] = ldcvt_h2(sAf + (size_t)(r0 + 8) * SAF + kc + 8);
            }
            #pragma unroll
            for (int ni = 0; ni < 8; ni++) {
                int n0 = wn * 64 + ni * 8 + gid;
                b[ni][0] = *(const uint32_t*)(sB + (size_t)n0 * SA + kc);
                b[ni][1] = *(const uint32_t*)(sB + (size_t)n0 * SA + kc + 8);
            }
            #pragma unroll
            for (int mi = 0; mi < 2; mi++)
                #pragma unroll
                for (int ni = 0; ni < 8; ni++)
                    mma16816(acc[mi][ni], a[mi], b[ni]);
        }
    }

    #pragma unroll
    for (int mi = 0; mi < 2; mi++) {
        int r = row0 + wm * 32 + mi * 16 + gid;
        #pragma unroll
        for (int ni = 0; ni < 8; ni++) {
            int cidx = wn * 64 + ni * 8 + tid4 * 2;
            if (r < N_TOT)
                *(__half2*)(C + (size_t)r * 256 + cidx) =
                    __floats2half2_rn(acc[mi][ni][0], acc[mi][ni][1]);
            if (r + 8 < N_TOT)
                *(__half2*)(C + (size_t)(r + 8) * 256 + cidx) =
                    __floats2half2_rn(acc[mi][ni][2], acc[mi][ni][3]);
        }
    }
}

// ---------------- SpMM: warp-per-row, 64-thread CTAs (2 rows) ----------
// Finer CTA granularity than 8-row blocks: same occupancy (32 CTAs/SM x
// 2 warps = 64 warps) but 4x smaller retirement unit -> smaller wave tail.
__device__ __forceinline__ void fma8(float* acc, float v, uint4 raw) {
    float2 f0 = __half22float2(*(__half2*)&raw.x);
    float2 f1 = __half22float2(*(__half2*)&raw.y);
    float2 f2 = __half22float2(*(__half2*)&raw.z);
    float2 f3 = __half22float2(*(__half2*)&raw.w);
    acc[0] = fmaf(v, f0.x, acc[0]);
    acc[1] = fmaf(v, f0.y, acc[1]);
    acc[2] = fmaf(v, f1.x, acc[2]);
    acc[3] = fmaf(v, f1.y, acc[3]);
    acc[4] = fmaf(v, f2.x, acc[4]);
    acc[5] = fmaf(v, f2.y, acc[5]);
    acc[6] = fmaf(v, f3.x, acc[6]);
    acc[7] = fmaf(v, f3.y, acc[7]);
}

__device__ __forceinline__ void spmm_row_w(const uint4* __restrict__ sup4,
                                           int row, int lane, float* acc) {
    int s = g_rowptr[row];
    int e = g_rowptr[row + 1];
    float acc1[8];
    #pragma unroll
    for (int q = 0; q < 8; q++) { acc[q] = 0.f; acc1[q] = 0.f; }
    int i = s;
    for (; i + 4 <= e; i += 4) {
        int2 e0 = __ldg(&g_edges[i]);
        int2 e1 = __ldg(&g_edges[i + 1]);
        int2 e2 = __ldg(&g_edges[i + 2]);
        int2 e3 = __ldg(&g_edges[i + 3]);
        uint4 r0 = __ldg(&sup4[(size_t)e0.x * 32 + lane]);
        uint4 r1 = __ldg(&sup4[(size_t)e1.x * 32 + lane]);
        uint4 r2 = __ldg(&sup4[(size_t)e2.x * 32 + lane]);
        uint4 r3 = __ldg(&sup4[(size_t)e3.x * 32 + lane]);
        fma8(acc,  __int_as_float(e0.y), r0);
        fma8(acc1, __int_as_float(e1.y), r1);
        fma8(acc,  __int_as_float(e2.y), r2);
        fma8(acc1, __int_as_float(e3.y), r3);
    }
    for (; i < e; i++) {
        int2 ed = __ldg(&g_edges[i]);
        uint4 r0 = __ldg(&sup4[(size_t)ed.x * 32 + lane]);
        fma8(acc, __int_as_float(ed.y), r0);
    }
    #pragma unroll
    for (int q = 0; q < 8; q++) acc[q] += acc1[q];
}

// writes next layer's fp16 A operand (stride 256)
__global__ void __launch_bounds__(64)
spmm_h16_kernel(const uint4* __restrict__ sup4,
                const float4* __restrict__ bias,
                __half* __restrict__ a_next, int nrows) {
    const int row  = blockIdx.x * 2 + (threadIdx.x >> 5);
    const int lane = threadIdx.x & 31;
    if (row >= nrows) return;
    float acc[8];
    spmm_row_w(sup4, row, lane, acc);
    float4 b0 = __ldg(&bias[lane * 2]);
    float4 b1 = __ldg(&bias[lane * 2 + 1]);
    float v0 = fmaxf(acc[0] + b0.x, 0.f), v1 = fmaxf(acc[1] + b0.y, 0.f);
    float v2 = fmaxf(acc[2] + b0.z, 0.f), v3 = fmaxf(acc[3] + b0.w, 0.f);
    float v4 = fmaxf(acc[4] + b1.x, 0.f), v5 = fmaxf(acc[5] + b1.y, 0.f);
    float v6 = fmaxf(acc[6] + b1.z, 0.f), v7 = fmaxf(acc[7] + b1.w, 0.f);
    __half2 h0 = __floats2half2_rn(v0, v1);
    __half2 h1 = __floats2half2_rn(v2, v3);
    __half2 h2 = __floats2half2_rn(v4, v5);
    __half2 h3 = __floats2half2_rn(v6, v7);
    uint4 o;
    o.x = *(uint32_t*)&h0; o.y = *(uint32_t*)&h1;
    o.z = *(uint32_t*)&h2; o.w = *(uint32_t*)&h3;
    *(uint4*)(a_next + (size_t)row * 256 + lane * 8) = o;
}

// Layer-3 SpMM fused with the output permutation.
__global__ void __launch_bounds__(64)
spmm_out_kernel(const uint4* __restrict__ sup4,
                const float4* __restrict__ bias,
                const int* __restrict__ pos,
                float4* __restrict__ out, int nrows) {
    const int row  = blockIdx.x * 2 + (threadIdx.x >> 5);
    const int lane = threadIdx.x & 31;
    if (row >= nrows) return;
    float acc[8];
    spmm_row_w(sup4, row, lane, acc);
    float4 b0 = __ldg(&bias[lane * 2]);
    float4 b1 = __ldg(&bias[lane * 2 + 1]);
    float4 o0, o1;
    o0.x = fmaxf(acc[0] + b0.x, 0.f); o0.y = fmaxf(acc[1] + b0.y, 0.f);
    o0.z = fmaxf(acc[2] + b0.z, 0.f); o0.w = fmaxf(acc[3] + b0.w, 0.f);
    o1.x = fmaxf(acc[4] + b1.x, 0.f); o1.y = fmaxf(acc[5] + b1.y, 0.f);
    o1.z = fmaxf(acc[6] + b1.z, 0.f); o1.w = fmaxf(acc[7] + b1.w, 0.f);
    size_t base = (size_t)__ldg(&pos[row]) * 64 + lane * 2;
    out[base]     = o0;
    out[base + 1] = o1;
}

// ---------------- output zero ----------------
__global__ void zero_out_kernel(float4* __restrict__ out, int n4) {
    int i = blockIdx.x * 256 + threadIdx.x;
    if (i < n4) out[i] = make_float4(0.f, 0.f, 0.f, 0.f);
}

// ---------------- launch ----------------
extern "C" void kernel_launch(void* const* d_in, const int* in_sizes, int n_in,
                              void* d_out, int out_size) {
    const float* x     = (const float*)d_in[0];
    const float* motif = (const float*)d_in[1];
    const int*   rows  = (const int*)d_in[2];
    const int*   cols  = (const int*)d_in[3];
    const float* vals  = (const float*)d_in[4];
    const int*   pos   = (const int*)d_in[5];
    int wi = 6;
    if (n_in >= 13 && in_sizes[6] == 1) wi = 7;
    const float* w1 = (const float*)d_in[wi + 0];
    const float* b1 = (const float*)d_in[wi + 1];
    const float* w2 = (const float*)d_in[wi + 2];
    const float* b2 = (const float*)d_in[wi + 3];
    const float* w3 = (const float*)d_in[wi + 4];
    const float* b3 = (const float*)d_in[wi + 5];

    __half *support, *a, *bt1, *bt2, *bt3;
    cudaGetSymbolAddress((void**)&support, g_support);
    cudaGetSymbolAddress((void**)&a, g_a);
    cudaGetSymbolAddress((void**)&bt1, g_b1);
    cudaGetSymbolAddress((void**)&bt2, g_b2);
    cudaGetSymbolAddress((void**)&bt3, g_b3);

    cudaFuncSetAttribute(hmma_gemm_kernel,
                         cudaFuncAttributeMaxDynamicSharedMemorySize, GEMM_SMEM);
    cudaFuncSetAttribute(hmma_gemm_f32a_kernel,
                         cudaFuncAttributeMaxDynamicSharedMemorySize, GEMMF_SMEM);

    // ONE side stream; created per call, intentionally not destroyed
    // mid-capture (graph-capture safety; two-wide graphs pass teardown).
    cudaStream_t s2;
    cudaStreamCreateWithFlags(&s2, cudaStreamNonBlocking);
    cudaEvent_t evFork, evJoin;
    cudaEventCreateWithFlags(&evFork, cudaEventDisableTiming);
    cudaEventCreateWithFlags(&evJoin, cudaEventDisableTiming);

    cudaEventRecord(evFork, 0);
    cudaStreamWaitEvent(s2, evFork, 0);

    const int gemm_grid = M_PAD / 64;    // 938, full-N CTAs
    const int spmm_grid = N_TOT / 2;     // 30000 (2 rows per 64-thread CTA)
    const int spmo_grid = N_XROWS / 2;   // 25000
    int n4 = out_size / 4;

    // --- side chain (s2): CSR build (parallel scan) + zero output ---
    zero_cnt_kernel<<<(N_TOT + 255) / 256, 256, 0, s2>>>();
    hist_kernel<<<E_TOT / 256, 256, 0, s2>>>(rows);
    scan_local_kernel<<<NB_SCAN, 1024, 0, s2>>>();
    scan_sums_kernel<<<1, 64, 0, s2>>>();
    scan_add_kernel<<<NB_SCAN, 1024, 0, s2>>>();
    scatter_edges_kernel<<<E_TOT / 256, 256, 0, s2>>>(rows, cols, vals);
    zero_out_kernel<<<(n4 + 255) / 256, 256, 0, s2>>>((float4*)d_out, n4);
    cudaEventRecord(evJoin, s2);

    // --- main chain: weights (one launch) + fused-convert layer-1 GEMM ---
    convertB3_kernel<<<1024, 256>>>(w1, w2, w3, bt1, bt2, bt3);
    hmma_gemm_f32a_kernel<<<gemm_grid, 256, GEMMF_SMEM>>>(x, motif, bt1,
                                                          support);

    // join: SpMM needs CSR; final spmm_out also needs zeroed output
    cudaStreamWaitEvent(0, evJoin, 0);
    spmm_h16_kernel<<<spmm_grid, 64>>>((const uint4*)support,
                                       (const float4*)b1, a, N_TOT);

    // --- layer 2 (K=256) ---
    hmma_gemm_kernel<<<gemm_grid, 256, GEMM_SMEM>>>(a, bt2, support, 256, N_TOT);
    spmm_h16_kernel<<<spmm_grid, 64>>>((const uint4*)support,
                                       (const float4*)b2, a, N_TOT);

    // --- layer 3 (K=256): SpMM fused with output scatter ---
    hmma_gemm_kernel<<<gemm_grid, 256, GEMM_SMEM>>>(a, bt3, support, 256, N_TOT);
    spmm_out_kernel<<<spmo_grid, 64>>>((const uint4*)support,
                                       (const float4*)b3, pos,
                                       (float4*)d_out, N_XROWS);
}